// round 4
// baseline (speedup 1.0000x reference)
#include <cuda_runtime.h>
#include <math.h>

#define B_SZ 4
#define S_LEN 2048
#define D_MODEL 2048
#define H_NUM 16
#define DH 128
#define D3 6144
#define NTOK (B_SZ * S_LEN)   // 8192

// -------- scratch (allocation-free rule: __device__ globals) --------
__device__ float g_xn [(size_t)NTOK * D_MODEL];   // 64 MB
__device__ float g_qkv[(size_t)NTOK * D3];        // 201 MB
__device__ float g_ctx[(size_t)NTOK * D_MODEL];   // 64 MB

// ===================== LayerNorm =====================
__global__ __launch_bounds__(256) void ln_kernel(
    const float* __restrict__ X, const float* __restrict__ w,
    const float* __restrict__ b, float* __restrict__ out)
{
    int row = blockIdx.x;
    int t = threadIdx.x;
    int lane = t & 31, wrp = t >> 5;
    const float* x = X + (size_t)row * D_MODEL;

    float4 v0 = *(const float4*)(x + t * 4);
    float4 v1 = *(const float4*)(x + 1024 + t * 4);

    float s  = v0.x + v0.y + v0.z + v0.w + v1.x + v1.y + v1.z + v1.w;
    float sq = v0.x*v0.x + v0.y*v0.y + v0.z*v0.z + v0.w*v0.w
             + v1.x*v1.x + v1.y*v1.y + v1.z*v1.z + v1.w*v1.w;

    #pragma unroll
    for (int off = 16; off; off >>= 1) {
        s  += __shfl_xor_sync(0xffffffffu, s,  off);
        sq += __shfl_xor_sync(0xffffffffu, sq, off);
    }
    __shared__ float sh_s[8], sh_q[8];
    if (lane == 0) { sh_s[wrp] = s; sh_q[wrp] = sq; }
    __syncthreads();
    float tot = 0.f, totq = 0.f;
    #pragma unroll
    for (int i = 0; i < 8; ++i) { tot += sh_s[i]; totq += sh_q[i]; }
    float mean = tot * (1.0f / D_MODEL);
    float var  = totq * (1.0f / D_MODEL) - mean * mean;
    float inv  = rsqrtf(var + 1e-5f);

    float* o = out + (size_t)row * D_MODEL;
    int c0 = t * 4, c1 = 1024 + t * 4;
    float4 w0 = *(const float4*)(w + c0), w1 = *(const float4*)(w + c1);
    float4 b0 = *(const float4*)(b + c0), b1 = *(const float4*)(b + c1);
    float4 r0, r1;
    r0.x = (v0.x - mean) * inv * w0.x + b0.x;
    r0.y = (v0.y - mean) * inv * w0.y + b0.y;
    r0.z = (v0.z - mean) * inv * w0.z + b0.z;
    r0.w = (v0.w - mean) * inv * w0.w + b0.w;
    r1.x = (v1.x - mean) * inv * w1.x + b1.x;
    r1.y = (v1.y - mean) * inv * w1.y + b1.y;
    r1.z = (v1.z - mean) * inv * w1.z + b1.z;
    r1.w = (v1.w - mean) * inv * w1.w + b1.w;
    *(float4*)(o + c0) = r0;
    *(float4*)(o + c1) = r1;
}

// ===================== SGEMM 128x128x8, 8x8 per thread =====================
__global__ __launch_bounds__(256) void sgemm128(
    const float* __restrict__ A, const float* __restrict__ B,
    const float* __restrict__ R, float* __restrict__ C,
    int M, int N, int K)
{
    __shared__ float As[8][128];
    __shared__ float Bs[8][128];

    int tid = threadIdx.x;
    int n0 = blockIdx.x * 128, m0 = blockIdx.y * 128;
    int tx = tid & 15, ty = tid >> 4;

    float acc[8][8];
    #pragma unroll
    for (int i = 0; i < 8; ++i)
        #pragma unroll
        for (int j = 0; j < 8; ++j) acc[i][j] = 0.f;

    int ar = tid >> 1, ak = (tid & 1) * 4;
    int bk = tid >> 5, bc = (tid & 31) * 4;
    const float* Ap = A + (size_t)(m0 + ar) * K + ak;
    const float* Bp = B + (size_t)bk * N + n0 + bc;

    for (int k0 = 0; k0 < K; k0 += 8) {
        float4 av = *(const float4*)(Ap + k0);
        As[ak + 0][ar] = av.x;
        As[ak + 1][ar] = av.y;
        As[ak + 2][ar] = av.z;
        As[ak + 3][ar] = av.w;
        *(float4*)&Bs[bk][bc] = *(const float4*)(Bp + (size_t)k0 * N);
        __syncthreads();

        #pragma unroll
        for (int k = 0; k < 8; ++k) {
            float a[8], bb[8];
            *(float4*)(a)      = *(float4*)&As[k][ty * 4];
            *(float4*)(a + 4)  = *(float4*)&As[k][64 + ty * 4];
            *(float4*)(bb)     = *(float4*)&Bs[k][tx * 4];
            *(float4*)(bb + 4) = *(float4*)&Bs[k][64 + tx * 4];
            #pragma unroll
            for (int i = 0; i < 8; ++i)
                #pragma unroll
                for (int j = 0; j < 8; ++j)
                    acc[i][j] = fmaf(a[i], bb[j], acc[i][j]);
        }
        __syncthreads();
    }

    #pragma unroll
    for (int i = 0; i < 8; ++i) {
        int row = m0 + ((i < 4) ? (ty * 4 + i) : (64 + ty * 4 + i - 4));
        #pragma unroll
        for (int jh = 0; jh < 2; ++jh) {
            int col = n0 + jh * 64 + tx * 4;
            size_t idx = (size_t)row * N + col;
            float4 o;
            o.x = acc[i][jh * 4 + 0];
            o.y = acc[i][jh * 4 + 1];
            o.z = acc[i][jh * 4 + 2];
            o.w = acc[i][jh * 4 + 3];
            if (R) {
                float4 r = *(const float4*)(R + idx);
                o.x += r.x; o.y += r.y; o.z += r.z; o.w += r.w;
            }
            *(float4*)(C + idx) = o;
        }
    }
}

// ===================== RoPE (in place on Q and K of qkv) =====================
__global__ __launch_bounds__(256) void rope_kernel(float* __restrict__ qkv)
{
    int t = blockIdx.x * blockDim.x + threadIdx.x;   // 4*2048*16*32 total
    int i = t & 31;
    int h = (t >> 5) & 15;
    int s = (t >> 9) & 2047;
    int b = t >> 20;
    if (b >= B_SZ) return;

    size_t base = ((size_t)(b * S_LEN + s)) * D3 + h * DH;
    double th = (double)s * pow(10000.0, -(double)i / 32.0);
    float c = (float)cos(th), sn = (float)sin(th);

    float* q = qkv + base + 2 * i;
    float x1 = q[0], x2 = q[1];
    q[0] = x1 * c - x2 * sn;
    q[1] = x2 * c + x1 * sn;

    float* k = qkv + base + D_MODEL + 2 * i;
    x1 = k[0]; x2 = k[1];
    k[0] = x1 * c - x2 * sn;
    k[1] = x2 * c + x1 * sn;
}

// ===================== Flash attention: BQ=BK=64, Dh=128 =====================
#define QS_STRIDE 129
#define KV_STRIDE 132
#define SS_STRIDE 68
#define ATTN_SMEM ((64 * QS_STRIDE + 64 * KV_STRIDE + 64 * SS_STRIDE + 192) * 4)

__global__ __launch_bounds__(256) void attn_kernel(
    const float* __restrict__ qkv, float* __restrict__ ctx)
{
    extern __shared__ float sm[];
    float* Qs = sm;                         // 64 x 129
    float* KV = Qs + 64 * QS_STRIDE;        // 64 x 132
    float* Ss = KV + 64 * KV_STRIDE;        // 64 x 68
    float* rm = Ss + 64 * SS_STRIDE;        // 64
    float* rl = rm + 64;                    // 64
    float* rc = rl + 64;                    // 64

    int qt = blockIdx.x, h = blockIdx.y, b = blockIdx.z;
    int tid = threadIdx.x;
    int w = tid >> 5, lane = tid & 31;
    int ty = tid >> 4, tx = tid & 15;
    int q0 = qt * 64;
    const float SCALE = 0.0883883476483184f;  // 1/sqrt(128)

    const float* qbase = qkv + ((size_t)(b * S_LEN + q0)) * D3 + h * DH;
    for (int idx = tid * 4; idx < 64 * 128; idx += 1024) {
        int r = idx >> 7, d = idx & 127;
        float4 v = *(const float4*)(qbase + (size_t)r * D3 + d);
        float* p = &Qs[r * QS_STRIDE + d];
        p[0] = v.x; p[1] = v.y; p[2] = v.z; p[3] = v.w;
    }
    if (tid < 64) { rm[tid] = -1e30f; rl[tid] = 0.f; }

    float acc[8][4];
    #pragma unroll
    for (int i = 0; i < 8; ++i)
        #pragma unroll
        for (int j = 0; j < 4; ++j) acc[i][j] = 0.f;

    for (int kt = 0; kt < S_LEN / 64; ++kt) {
        __syncthreads();  // prior PV reads of KV done; also fences Q/rm init
        const float* kbase = qkv + ((size_t)(b * S_LEN + kt * 64)) * D3 + D_MODEL + h * DH;
        for (int idx = tid * 4; idx < 64 * 128; idx += 1024) {
            int r = idx >> 7, d = idx & 127;
            *(float4*)&KV[r * KV_STRIDE + d] = *(const float4*)(kbase + (size_t)r * D3 + d);
        }
        __syncthreads();

        // scores: rows 4*ty+i, cols tx+16*j
        float sc[4][4];
        #pragma unroll
        for (int i = 0; i < 4; ++i)
            #pragma unroll
            for (int j = 0; j < 4; ++j) sc[i][j] = 0.f;
        const float* qr = &Qs[(4 * ty) * QS_STRIDE];
        const float* kr = &KV[tx * KV_STRIDE];
        #pragma unroll 4
        for (int d = 0; d < 128; ++d) {
            float a0 = qr[0 * QS_STRIDE + d];
            float a1 = qr[1 * QS_STRIDE + d];
            float a2 = qr[2 * QS_STRIDE + d];
            float a3 = qr[3 * QS_STRIDE + d];
            float b0 = kr[0 * KV_STRIDE + d];
            float b1 = kr[16 * KV_STRIDE + d];
            float b2 = kr[32 * KV_STRIDE + d];
            float b3 = kr[48 * KV_STRIDE + d];
            sc[0][0] = fmaf(a0, b0, sc[0][0]); sc[0][1] = fmaf(a0, b1, sc[0][1]);
            sc[0][2] = fmaf(a0, b2, sc[0][2]); sc[0][3] = fmaf(a0, b3, sc[0][3]);
            sc[1][0] = fmaf(a1, b0, sc[1][0]); sc[1][1] = fmaf(a1, b1, sc[1][1]);
            sc[1][2] = fmaf(a1, b2, sc[1][2]); sc[1][3] = fmaf(a1, b3, sc[1][3]);
            sc[2][0] = fmaf(a2, b0, sc[2][0]); sc[2][1] = fmaf(a2, b1, sc[2][1]);
            sc[2][2] = fmaf(a2, b2, sc[2][2]); sc[2][3] = fmaf(a2, b3, sc[2][3]);
            sc[3][0] = fmaf(a3, b0, sc[3][0]); sc[3][1] = fmaf(a3, b1, sc[3][1]);
            sc[3][2] = fmaf(a3, b2, sc[3][2]); sc[3][3] = fmaf(a3, b3, sc[3][3]);
        }
        #pragma unroll
        for (int i = 0; i < 4; ++i)
            #pragma unroll
            for (int j = 0; j < 4; ++j)
                Ss[(4 * ty + i) * SS_STRIDE + tx + 16 * j] = sc[i][j] * SCALE;
        __syncthreads();

        // load V into KV (K reads complete) while doing softmax on Ss
        const float* vbase = qkv + ((size_t)(b * S_LEN + kt * 64)) * D3 + 2 * D_MODEL + h * DH;
        for (int idx = tid * 4; idx < 64 * 128; idx += 1024) {
            int r = idx >> 7, d = idx & 127;
            *(float4*)&KV[r * KV_STRIDE + d] = *(const float4*)(vbase + (size_t)r * D3 + d);
        }
        // online softmax: warp w owns rows 8w..8w+7
        #pragma unroll
        for (int rr = 0; rr < 8; ++rr) {
            int r = 8 * w + rr;
            float v0 = Ss[r * SS_STRIDE + lane];
            float v1 = Ss[r * SS_STRIDE + lane + 32];
            float mx = fmaxf(v0, v1);
            #pragma unroll
            for (int off = 16; off; off >>= 1)
                mx = fmaxf(mx, __shfl_xor_sync(0xffffffffu, mx, off));
            float m_old = rm[r];
            float m_new = fmaxf(m_old, mx);
            float p0 = expf(v0 - m_new), p1 = expf(v1 - m_new);
            Ss[r * SS_STRIDE + lane] = p0;
            Ss[r * SS_STRIDE + lane + 32] = p1;
            float su = p0 + p1;
            #pragma unroll
            for (int off = 16; off; off >>= 1)
                su += __shfl_xor_sync(0xffffffffu, su, off);
            if (lane == 0) {
                float corr = expf(m_old - m_new);
                rc[r] = corr;
                rl[r] = rl[r] * corr + su;
                rm[r] = m_new;
            }
        }
        __syncthreads();

        // rescale + PV: warp w rows 8w..8w+7, cols lane*4..lane*4+3
        #pragma unroll
        for (int rr = 0; rr < 8; ++rr) {
            float c = rc[8 * w + rr];
            acc[rr][0] *= c; acc[rr][1] *= c; acc[rr][2] *= c; acc[rr][3] *= c;
        }
        for (int j = 0; j < 64; ++j) {
            float4 v = *(const float4*)&KV[j * KV_STRIDE + lane * 4];
            #pragma unroll
            for (int rr = 0; rr < 8; ++rr) {
                float p = Ss[(8 * w + rr) * SS_STRIDE + j];
                acc[rr][0] = fmaf(p, v.x, acc[rr][0]);
                acc[rr][1] = fmaf(p, v.y, acc[rr][1]);
                acc[rr][2] = fmaf(p, v.z, acc[rr][2]);
                acc[rr][3] = fmaf(p, v.w, acc[rr][3]);
            }
        }
    }

    // epilogue
    #pragma unroll
    for (int rr = 0; rr < 8; ++rr) {
        int r = 8 * w + rr;
        float inv = 1.0f / rl[r];
        float4 o;
        o.x = acc[rr][0] * inv; o.y = acc[rr][1] * inv;
        o.z = acc[rr][2] * inv; o.w = acc[rr][3] * inv;
        size_t idx = ((size_t)(b * S_LEN + q0 + r)) * D_MODEL + h * DH + lane * 4;
        *(float4*)(ctx + idx) = o;
    }
}

// ===================== launcher =====================
extern "C" void kernel_launch(void* const* d_in, const int* in_sizes, int n_in,
                              void* d_out, int out_size)
{
    const float* X     = (const float*)d_in[0];
    const float* ln_w  = (const float*)d_in[1];
    const float* ln_b  = (const float*)d_in[2];
    const float* W_in  = (const float*)d_in[3];
    const float* W_out = (const float*)d_in[4];
    float* out = (float*)d_out;

    float *xn, *qkv, *ctx;
    cudaGetSymbolAddress((void**)&xn,  g_xn);
    cudaGetSymbolAddress((void**)&qkv, g_qkv);
    cudaGetSymbolAddress((void**)&ctx, g_ctx);

    ln_kernel<<<NTOK, 256>>>(X, ln_w, ln_b, xn);

    dim3 g1(D3 / 128, NTOK / 128);
    sgemm128<<<g1, 256>>>(xn, W_in, nullptr, qkv, NTOK, D3, D_MODEL);

    rope_kernel<<<(B_SZ * S_LEN * H_NUM * 32) / 256, 256>>>(qkv);

    cudaFuncSetAttribute(attn_kernel, cudaFuncAttributeMaxDynamicSharedMemorySize, ATTN_SMEM);
    attn_kernel<<<dim3(S_LEN / 64, H_NUM, B_SZ), 256, ATTN_SMEM>>>(qkv, ctx);

    dim3 g2(D_MODEL / 128, NTOK / 128);
    sgemm128<<<g2, 256>>>(ctx, W_out, X, out, NTOK, D_MODEL, D_MODEL);
}

// round 6
// speedup vs baseline: 1.3860x; 1.3860x over previous
#include <cuda_runtime.h>
#include <math.h>

#define B_SZ 4
#define S_LEN 2048
#define D_MODEL 2048
#define H_NUM 16
#define DH 128
#define D3 6144
#define NTOK (B_SZ * S_LEN)   // 8192

// -------- scratch (allocation-free rule: __device__ globals) --------
__device__ float g_xn  [(size_t)NTOK * D_MODEL];     // 64 MB  (tf32-rounded LN out)
__device__ float g_qkv [(size_t)NTOK * D3];          // 201 MB
__device__ float g_ctx [(size_t)NTOK * D_MODEL];     // 64 MB  (tf32-rounded ctx)
__device__ float g_win [(size_t)D_MODEL * D3];       // 48 MB  (tf32-rounded W_in)
__device__ float g_wout[(size_t)D_MODEL * D_MODEL];  // 16 MB  (tf32-rounded W_out)

// ---------- helpers ----------
__device__ __forceinline__ float tf32r(float x) {
    unsigned u;
    asm("cvt.rna.tf32.f32 %0, %1;" : "=r"(u) : "f"(x));
    return __uint_as_float(u);
}

#define CP_ASYNC16(dst, src) \
    asm volatile("cp.async.cg.shared.global [%0], [%1], 16;" :: "r"(dst), "l"(src))
#define CP_COMMIT() asm volatile("cp.async.commit_group;")

__device__ __forceinline__ void mma_tf32(float* c, const unsigned* a, const unsigned* b) {
    asm volatile(
        "mma.sync.aligned.m16n8k8.row.col.f32.tf32.tf32.f32 "
        "{%0,%1,%2,%3}, {%4,%5,%6,%7}, {%8,%9}, {%0,%1,%2,%3};"
        : "+f"(c[0]), "+f"(c[1]), "+f"(c[2]), "+f"(c[3])
        : "r"(a[0]), "r"(a[1]), "r"(a[2]), "r"(a[3]), "r"(b[0]), "r"(b[1]));
}

// ===================== weight tf32 rounding (runs every call, ~16us) ============
__global__ __launch_bounds__(256) void wcvt_kernel(
    const float* __restrict__ in, float* __restrict__ out, int n)
{
    int i = (blockIdx.x * 256 + threadIdx.x) * 4;
    if (i >= n) return;
    float4 v = *(const float4*)(in + i);
    v.x = tf32r(v.x); v.y = tf32r(v.y); v.z = tf32r(v.z); v.w = tf32r(v.w);
    *(float4*)(out + i) = v;
}

// ===================== LayerNorm (tf32-rounds its output) =====================
__global__ __launch_bounds__(256) void ln_kernel(
    const float* __restrict__ X, const float* __restrict__ w,
    const float* __restrict__ b, float* __restrict__ out)
{
    int row = blockIdx.x;
    int t = threadIdx.x;
    int lane = t & 31, wrp = t >> 5;
    const float* x = X + (size_t)row * D_MODEL;

    float4 v0 = *(const float4*)(x + t * 4);
    float4 v1 = *(const float4*)(x + 1024 + t * 4);

    float s  = v0.x + v0.y + v0.z + v0.w + v1.x + v1.y + v1.z + v1.w;
    float sq = v0.x*v0.x + v0.y*v0.y + v0.z*v0.z + v0.w*v0.w
             + v1.x*v1.x + v1.y*v1.y + v1.z*v1.z + v1.w*v1.w;

    #pragma unroll
    for (int off = 16; off; off >>= 1) {
        s  += __shfl_xor_sync(0xffffffffu, s,  off);
        sq += __shfl_xor_sync(0xffffffffu, sq, off);
    }
    __shared__ float sh_s[8], sh_q[8];
    if (lane == 0) { sh_s[wrp] = s; sh_q[wrp] = sq; }
    __syncthreads();
    float tot = 0.f, totq = 0.f;
    #pragma unroll
    for (int i = 0; i < 8; ++i) { tot += sh_s[i]; totq += sh_q[i]; }
    float mean = tot * (1.0f / D_MODEL);
    float var  = totq * (1.0f / D_MODEL) - mean * mean;
    float inv  = rsqrtf(var + 1e-5f);

    float* o = out + (size_t)row * D_MODEL;
    int c0 = t * 4, c1 = 1024 + t * 4;
    float4 w0 = *(const float4*)(w + c0), w1 = *(const float4*)(w + c1);
    float4 b0 = *(const float4*)(b + c0), b1 = *(const float4*)(b + c1);
    float4 r0, r1;
    r0.x = tf32r((v0.x - mean) * inv * w0.x + b0.x);
    r0.y = tf32r((v0.y - mean) * inv * w0.y + b0.y);
    r0.z = tf32r((v0.z - mean) * inv * w0.z + b0.z);
    r0.w = tf32r((v0.w - mean) * inv * w0.w + b0.w);
    r1.x = tf32r((v1.x - mean) * inv * w1.x + b1.x);
    r1.y = tf32r((v1.y - mean) * inv * w1.y + b1.y);
    r1.z = tf32r((v1.z - mean) * inv * w1.z + b1.z);
    r1.w = tf32r((v1.w - mean) * inv * w1.w + b1.w);
    *(float4*)(o + c0) = r0;
    *(float4*)(o + c1) = r1;
}

// ===================== TF32 tensor-core GEMM: 128x128x32, cp.async 2-stage =====
// A: MxK row-major (tf32-rounded), B: KxN row-major (tf32-rounded),
// C = A*B (+R). 256 threads, warp grid 2(m) x 4(n), warp tile 64x32.
#define AS_STRIDE 36          // floats; banks (4g+tig) -> conflict-free A frags
#define BS_STRIDE 136         // floats; banks (8tig+g) -> conflict-free B frags
#define AS_FLOATS (128 * AS_STRIDE)            // 4608
#define BS_FLOATS (32 * BS_STRIDE)             // 4352
#define STAGE_FLOATS (AS_FLOATS + BS_FLOATS)   // 8960
#define GEMM_SMEM (2 * STAGE_FLOATS * 4)       // 71680 bytes

__device__ __forceinline__ void gemm_load_tile(
    const float* __restrict__ A, const float* __restrict__ B,
    int K, int N, int m0, int n0, int k0, unsigned sbase, int tid)
{
    int ar = tid >> 1, ac = (tid & 1) * 16;
    const float* ap = A + (size_t)(m0 + ar) * K + k0 + ac;
    unsigned ad = sbase + (unsigned)(ar * AS_STRIDE + ac) * 4u;
    #pragma unroll
    for (int j = 0; j < 4; ++j) CP_ASYNC16(ad + j * 16, ap + j * 4);

    int br = tid >> 3, bc = (tid & 7) * 16;
    const float* bp = B + (size_t)(k0 + br) * N + n0 + bc;
    unsigned bd = sbase + (unsigned)AS_FLOATS * 4u + (unsigned)(br * BS_STRIDE + bc) * 4u;
    #pragma unroll
    for (int j = 0; j < 4; ++j) CP_ASYNC16(bd + j * 16, bp + j * 4);
}

__global__ __launch_bounds__(256) void sgemm_tf32(
    const float* __restrict__ A, const float* __restrict__ B,
    const float* __restrict__ R, float* __restrict__ C,
    int M, int N, int K)
{
    extern __shared__ float sm[];
    unsigned sbase = (unsigned)__cvta_generic_to_shared(sm);

    int tid = threadIdx.x;
    int wid = tid >> 5, lane = tid & 31;
    int g = lane >> 2, tig = lane & 3;
    int warp_m = wid & 1, warp_n = wid >> 1;
    int m0 = blockIdx.y * 128, n0 = blockIdx.x * 128;
    int am = warp_m * 64, bn = warp_n * 32;

    float acc[4][4][4];
    #pragma unroll
    for (int i = 0; i < 4; ++i)
        #pragma unroll
        for (int j = 0; j < 4; ++j)
            #pragma unroll
            for (int r = 0; r < 4; ++r) acc[i][j][r] = 0.f;

    const int NT = K / 32;
    gemm_load_tile(A, B, K, N, m0, n0, 0, sbase, tid);
    CP_COMMIT();

    int buf = 0;
    for (int kt = 0; kt < NT; ++kt) {
        if (kt + 1 < NT) {
            gemm_load_tile(A, B, K, N, m0, n0, (kt + 1) * 32,
                           sbase + (unsigned)((buf ^ 1) * STAGE_FLOATS * 4), tid);
            CP_COMMIT();
            asm volatile("cp.async.wait_group 1;");
        } else {
            asm volatile("cp.async.wait_group 0;");
        }
        __syncthreads();

        const float* As = sm + buf * STAGE_FLOATS;
        const float* Bs = As + AS_FLOATS;

        #pragma unroll
        for (int s = 0; s < 4; ++s) {
            int ks = s * 8;
            unsigned a[4][4], bfr[4][2];
            #pragma unroll
            for (int i = 0; i < 4; ++i) {
                const float* p = As + (am + i * 16 + g) * AS_STRIDE + ks + tig;
                a[i][0] = __float_as_uint(p[0]);
                a[i][1] = __float_as_uint(p[8 * AS_STRIDE]);
                a[i][2] = __float_as_uint(p[4]);
                a[i][3] = __float_as_uint(p[8 * AS_STRIDE + 4]);
            }
            #pragma unroll
            for (int j = 0; j < 4; ++j) {
                const float* p = Bs + (ks + tig) * BS_STRIDE + bn + j * 8 + g;
                bfr[j][0] = __float_as_uint(p[0]);
                bfr[j][1] = __float_as_uint(p[4 * BS_STRIDE]);
            }
            #pragma unroll
            for (int i = 0; i < 4; ++i)
                #pragma unroll
                for (int j = 0; j < 4; ++j)
                    mma_tf32(acc[i][j], a[i], bfr[j]);
        }
        __syncthreads();
        buf ^= 1;
    }

    // epilogue: c0,c1 -> (row g, cols 2tig,2tig+1); c2,c3 -> (row g+8)
    #pragma unroll
    for (int i = 0; i < 4; ++i) {
        int row0 = m0 + am + i * 16 + g;
        #pragma unroll
        for (int j = 0; j < 4; ++j) {
            int col = n0 + bn + j * 8 + 2 * tig;
            size_t idx0 = (size_t)row0 * N + col;
            size_t idx1 = idx0 + (size_t)8 * N;
            float2 o0 = make_float2(acc[i][j][0], acc[i][j][1]);
            float2 o1 = make_float2(acc[i][j][2], acc[i][j][3]);
            if (R) {
                float2 r0 = *(const float2*)(R + idx0);
                float2 r1 = *(const float2*)(R + idx1);
                o0.x += r0.x; o0.y += r0.y;
                o1.x += r1.x; o1.y += r1.y;
            }
            *(float2*)(C + idx0) = o0;
            *(float2*)(C + idx1) = o1;
        }
    }
}

// ===================== RoPE (in place on Q and K of qkv) =====================
__global__ __launch_bounds__(256) void rope_kernel(float* __restrict__ qkv)
{
    int t = blockIdx.x * blockDim.x + threadIdx.x;   // 4*2048*16*32 total
    int i = t & 31;
    int h = (t >> 5) & 15;
    int s = (t >> 9) & 2047;
    int b = t >> 20;
    if (b >= B_SZ) return;

    size_t base = ((size_t)(b * S_LEN + s)) * D3 + h * DH;
    double th = (double)s * pow(10000.0, -(double)i / 32.0);
    float c = (float)cos(th), sn = (float)sin(th);

    float* q = qkv + base + 2 * i;
    float x1 = q[0], x2 = q[1];
    q[0] = x1 * c - x2 * sn;
    q[1] = x2 * c + x1 * sn;

    float* k = qkv + base + D_MODEL + 2 * i;
    x1 = k[0]; x2 = k[1];
    k[0] = x1 * c - x2 * sn;
    k[1] = x2 * c + x1 * sn;
}

// ===================== Flash attention: BQ=BK=64, Dh=128 (fp32) ================
#define QS_STRIDE 129
#define KV_STRIDE 132
#define SS_STRIDE 68
#define ATTN_SMEM ((64 * QS_STRIDE + 64 * KV_STRIDE + 64 * SS_STRIDE + 192) * 4)

__global__ __launch_bounds__(256) void attn_kernel(
    const float* __restrict__ qkv, float* __restrict__ ctx)
{
    extern __shared__ float sm[];
    float* Qs = sm;                         // 64 x 129
    float* KV = Qs + 64 * QS_STRIDE;        // 64 x 132
    float* Ss = KV + 64 * KV_STRIDE;        // 64 x 68
    float* rm = Ss + 64 * SS_STRIDE;        // 64
    float* rl = rm + 64;                    // 64
    float* rc = rl + 64;                    // 64

    int qt = blockIdx.x, h = blockIdx.y, b = blockIdx.z;
    int tid = threadIdx.x;
    int w = tid >> 5, lane = tid & 31;
    int ty = tid >> 4, tx = tid & 15;
    int q0 = qt * 64;
    const float SCALE = 0.0883883476483184f;  // 1/sqrt(128)

    const float* qbase = qkv + ((size_t)(b * S_LEN + q0)) * D3 + h * DH;
    for (int idx = tid * 4; idx < 64 * 128; idx += 1024) {
        int r = idx >> 7, d = idx & 127;
        float4 v = *(const float4*)(qbase + (size_t)r * D3 + d);
        float* p = &Qs[r * QS_STRIDE + d];
        p[0] = v.x; p[1] = v.y; p[2] = v.z; p[3] = v.w;
    }
    if (tid < 64) { rm[tid] = -1e30f; rl[tid] = 0.f; }

    float acc[8][4];
    #pragma unroll
    for (int i = 0; i < 8; ++i)
        #pragma unroll
        for (int j = 0; j < 4; ++j) acc[i][j] = 0.f;

    for (int kt = 0; kt < S_LEN / 64; ++kt) {
        __syncthreads();  // prior PV reads of KV done; also fences Q/rm init
        const float* kbase = qkv + ((size_t)(b * S_LEN + kt * 64)) * D3 + D_MODEL + h * DH;
        for (int idx = tid * 4; idx < 64 * 128; idx += 1024) {
            int r = idx >> 7, d = idx & 127;
            *(float4*)&KV[r * KV_STRIDE + d] = *(const float4*)(kbase + (size_t)r * D3 + d);
        }
        __syncthreads();

        // scores: rows 4*ty+i, cols tx+16*j
        float sc[4][4];
        #pragma unroll
        for (int i = 0; i < 4; ++i)
            #pragma unroll
            for (int j = 0; j < 4; ++j) sc[i][j] = 0.f;
        const float* qr = &Qs[(4 * ty) * QS_STRIDE];
        const float* kr = &KV[tx * KV_STRIDE];
        #pragma unroll 4
        for (int d = 0; d < 128; ++d) {
            float a0 = qr[0 * QS_STRIDE + d];
            float a1 = qr[1 * QS_STRIDE + d];
            float a2 = qr[2 * QS_STRIDE + d];
            float a3 = qr[3 * QS_STRIDE + d];
            float b0 = kr[0 * KV_STRIDE + d];
            float b1 = kr[16 * KV_STRIDE + d];
            float b2 = kr[32 * KV_STRIDE + d];
            float b3 = kr[48 * KV_STRIDE + d];
            sc[0][0] = fmaf(a0, b0, sc[0][0]); sc[0][1] = fmaf(a0, b1, sc[0][1]);
            sc[0][2] = fmaf(a0, b2, sc[0][2]); sc[0][3] = fmaf(a0, b3, sc[0][3]);
            sc[1][0] = fmaf(a1, b0, sc[1][0]); sc[1][1] = fmaf(a1, b1, sc[1][1]);
            sc[1][2] = fmaf(a1, b2, sc[1][2]); sc[1][3] = fmaf(a1, b3, sc[1][3]);
            sc[2][0] = fmaf(a2, b0, sc[2][0]); sc[2][1] = fmaf(a2, b1, sc[2][1]);
            sc[2][2] = fmaf(a2, b2, sc[2][2]); sc[2][3] = fmaf(a2, b3, sc[2][3]);
            sc[3][0] = fmaf(a3, b0, sc[3][0]); sc[3][1] = fmaf(a3, b1, sc[3][1]);
            sc[3][2] = fmaf(a3, b2, sc[3][2]); sc[3][3] = fmaf(a3, b3, sc[3][3]);
        }
        #pragma unroll
        for (int i = 0; i < 4; ++i)
            #pragma unroll
            for (int j = 0; j < 4; ++j)
                Ss[(4 * ty + i) * SS_STRIDE + tx + 16 * j] = sc[i][j] * SCALE;
        __syncthreads();

        // load V into KV (K reads complete) while doing softmax on Ss
        const float* vbase = qkv + ((size_t)(b * S_LEN + kt * 64)) * D3 + 2 * D_MODEL + h * DH;
        for (int idx = tid * 4; idx < 64 * 128; idx += 1024) {
            int r = idx >> 7, d = idx & 127;
            *(float4*)&KV[r * KV_STRIDE + d] = *(const float4*)(vbase + (size_t)r * D3 + d);
        }
        // online softmax: warp w owns rows 8w..8w+7
        #pragma unroll
        for (int rr = 0; rr < 8; ++rr) {
            int r = 8 * w + rr;
            float v0 = Ss[r * SS_STRIDE + lane];
            float v1 = Ss[r * SS_STRIDE + lane + 32];
            float mx = fmaxf(v0, v1);
            #pragma unroll
            for (int off = 16; off; off >>= 1)
                mx = fmaxf(mx, __shfl_xor_sync(0xffffffffu, mx, off));
            float m_old = rm[r];
            float m_new = fmaxf(m_old, mx);
            float p0 = expf(v0 - m_new), p1 = expf(v1 - m_new);
            Ss[r * SS_STRIDE + lane] = p0;
            Ss[r * SS_STRIDE + lane + 32] = p1;
            float su = p0 + p1;
            #pragma unroll
            for (int off = 16; off; off >>= 1)
                su += __shfl_xor_sync(0xffffffffu, su, off);
            if (lane == 0) {
                float corr = expf(m_old - m_new);
                rc[r] = corr;
                rl[r] = rl[r] * corr + su;
                rm[r] = m_new;
            }
        }
        __syncthreads();

        // rescale + PV: warp w rows 8w..8w+7, cols lane*4..lane*4+3
        #pragma unroll
        for (int rr = 0; rr < 8; ++rr) {
            float c = rc[8 * w + rr];
            acc[rr][0] *= c; acc[rr][1] *= c; acc[rr][2] *= c; acc[rr][3] *= c;
        }
        for (int j = 0; j < 64; ++j) {
            float4 v = *(const float4*)&KV[j * KV_STRIDE + lane * 4];
            #pragma unroll
            for (int rr = 0; rr < 8; ++rr) {
                float p = Ss[(8 * w + rr) * SS_STRIDE + j];
                acc[rr][0] = fmaf(p, v.x, acc[rr][0]);
                acc[rr][1] = fmaf(p, v.y, acc[rr][1]);
                acc[rr][2] = fmaf(p, v.z, acc[rr][2]);
                acc[rr][3] = fmaf(p, v.w, acc[rr][3]);
            }
        }
    }

    // epilogue (tf32-round ctx: it feeds the TF32 out-projection GEMM)
    #pragma unroll
    for (int rr = 0; rr < 8; ++rr) {
        int r = 8 * w + rr;
        float inv = 1.0f / rl[r];
        float4 o;
        o.x = tf32r(acc[rr][0] * inv); o.y = tf32r(acc[rr][1] * inv);
        o.z = tf32r(acc[rr][2] * inv); o.w = tf32r(acc[rr][3] * inv);
        size_t idx = ((size_t)(b * S_LEN + q0 + r)) * D_MODEL + h * DH + lane * 4;
        *(float4*)(ctx + idx) = o;
    }
}

// ===================== launcher =====================
extern "C" void kernel_launch(void* const* d_in, const int* in_sizes, int n_in,
                              void* d_out, int out_size)
{
    const float* X     = (const float*)d_in[0];
    const float* ln_w  = (const float*)d_in[1];
    const float* ln_b  = (const float*)d_in[2];
    const float* W_in  = (const float*)d_in[3];
    const float* W_out = (const float*)d_in[4];
    float* out = (float*)d_out;

    float *xn, *qkv, *ctx, *win, *wout;
    cudaGetSymbolAddress((void**)&xn,   g_xn);
    cudaGetSymbolAddress((void**)&qkv,  g_qkv);
    cudaGetSymbolAddress((void**)&ctx,  g_ctx);
    cudaGetSymbolAddress((void**)&win,  g_win);
    cudaGetSymbolAddress((void**)&wout, g_wout);

    // round weights to tf32 (unbiased RN) once per call
    {
        int n1 = D_MODEL * D3;
        int n2 = D_MODEL * D_MODEL;
        wcvt_kernel<<<n1 / 1024, 256>>>(W_in,  win,  n1);
        wcvt_kernel<<<n2 / 1024, 256>>>(W_out, wout, n2);
    }

    ln_kernel<<<NTOK, 256>>>(X, ln_w, ln_b, xn);

    cudaFuncSetAttribute(sgemm_tf32, cudaFuncAttributeMaxDynamicSharedMemorySize, GEMM_SMEM);

    dim3 g1(D3 / 128, NTOK / 128);
    sgemm_tf32<<<g1, 256, GEMM_SMEM>>>(xn, win, nullptr, qkv, NTOK, D3, D_MODEL);

    rope_kernel<<<(B_SZ * S_LEN * H_NUM * 32) / 256, 256>>>(qkv);

    cudaFuncSetAttribute(attn_kernel, cudaFuncAttributeMaxDynamicSharedMemorySize, ATTN_SMEM);
    attn_kernel<<<dim3(S_LEN / 64, H_NUM, B_SZ), 256, ATTN_SMEM>>>(qkv, ctx);

    dim3 g2(D_MODEL / 128, NTOK / 128);
    sgemm_tf32<<<g2, 256, GEMM_SMEM>>>(ctx, wout, X, out, NTOK, D_MODEL, D_MODEL);
}

// round 8
// speedup vs baseline: 2.0031x; 1.4452x over previous
#include <cuda_runtime.h>
#include <math.h>

#define B_SZ 4
#define S_LEN 2048
#define D_MODEL 2048
#define H_NUM 16
#define DH 128
#define D3 6144
#define NTOK (B_SZ * S_LEN)   // 8192

// -------- scratch (allocation-free rule: __device__ globals) --------
__device__ float g_xn  [(size_t)NTOK * D_MODEL];     // 64 MB  (tf32-rounded LN out)
__device__ float g_qkv [(size_t)NTOK * D3];          // 201 MB (tf32-rounded post-rope)
__device__ float g_ctx [(size_t)NTOK * D_MODEL];     // 64 MB  (tf32-rounded ctx)
__device__ float g_win [(size_t)D_MODEL * D3];       // 48 MB  (tf32-rounded W_in)
__device__ float g_wout[(size_t)D_MODEL * D_MODEL];  // 16 MB  (tf32-rounded W_out)

// ---------- helpers ----------
__device__ __forceinline__ float tf32r(float x) {
    unsigned u;
    asm("cvt.rna.tf32.f32 %0, %1;" : "=r"(u) : "f"(x));
    return __uint_as_float(u);
}

#define CP_ASYNC16(dst, src) \
    asm volatile("cp.async.cg.shared.global [%0], [%1], 16;" :: "r"(dst), "l"(src))
#define CP_COMMIT() asm volatile("cp.async.commit_group;")

__device__ __forceinline__ void mma_tf32(float* c, const unsigned* a, const unsigned* b) {
    asm volatile(
        "mma.sync.aligned.m16n8k8.row.col.f32.tf32.tf32.f32 "
        "{%0,%1,%2,%3}, {%4,%5,%6,%7}, {%8,%9}, {%0,%1,%2,%3};"
        : "+f"(c[0]), "+f"(c[1]), "+f"(c[2]), "+f"(c[3])
        : "r"(a[0]), "r"(a[1]), "r"(a[2]), "r"(a[3]), "r"(b[0]), "r"(b[1]));
}

// ===================== weight tf32 rounding =====================
__global__ __launch_bounds__(256) void wcvt_kernel(
    const float* __restrict__ in, float* __restrict__ out, int n)
{
    int i = (blockIdx.x * 256 + threadIdx.x) * 4;
    if (i >= n) return;
    float4 v = *(const float4*)(in + i);
    v.x = tf32r(v.x); v.y = tf32r(v.y); v.z = tf32r(v.z); v.w = tf32r(v.w);
    *(float4*)(out + i) = v;
}

// ===================== LayerNorm (tf32-rounds its output) =====================
__global__ __launch_bounds__(256) void ln_kernel(
    const float* __restrict__ X, const float* __restrict__ w,
    const float* __restrict__ b, float* __restrict__ out)
{
    int row = blockIdx.x;
    int t = threadIdx.x;
    int lane = t & 31, wrp = t >> 5;
    const float* x = X + (size_t)row * D_MODEL;

    float4 v0 = *(const float4*)(x + t * 4);
    float4 v1 = *(const float4*)(x + 1024 + t * 4);

    float s  = v0.x + v0.y + v0.z + v0.w + v1.x + v1.y + v1.z + v1.w;
    float sq = v0.x*v0.x + v0.y*v0.y + v0.z*v0.z + v0.w*v0.w
             + v1.x*v1.x + v1.y*v1.y + v1.z*v1.z + v1.w*v1.w;

    #pragma unroll
    for (int off = 16; off; off >>= 1) {
        s  += __shfl_xor_sync(0xffffffffu, s,  off);
        sq += __shfl_xor_sync(0xffffffffu, sq, off);
    }
    __shared__ float sh_s[8], sh_q[8];
    if (lane == 0) { sh_s[wrp] = s; sh_q[wrp] = sq; }
    __syncthreads();
    float tot = 0.f, totq = 0.f;
    #pragma unroll
    for (int i = 0; i < 8; ++i) { tot += sh_s[i]; totq += sh_q[i]; }
    float mean = tot * (1.0f / D_MODEL);
    float var  = totq * (1.0f / D_MODEL) - mean * mean;
    float inv  = rsqrtf(var + 1e-5f);

    float* o = out + (size_t)row * D_MODEL;
    int c0 = t * 4, c1 = 1024 + t * 4;
    float4 w0 = *(const float4*)(w + c0), w1 = *(const float4*)(w + c1);
    float4 b0 = *(const float4*)(b + c0), b1 = *(const float4*)(b + c1);
    float4 r0, r1;
    r0.x = tf32r((v0.x - mean) * inv * w0.x + b0.x);
    r0.y = tf32r((v0.y - mean) * inv * w0.y + b0.y);
    r0.z = tf32r((v0.z - mean) * inv * w0.z + b0.z);
    r0.w = tf32r((v0.w - mean) * inv * w0.w + b0.w);
    r1.x = tf32r((v1.x - mean) * inv * w1.x + b1.x);
    r1.y = tf32r((v1.y - mean) * inv * w1.y + b1.y);
    r1.z = tf32r((v1.z - mean) * inv * w1.z + b1.z);
    r1.w = tf32r((v1.w - mean) * inv * w1.w + b1.w);
    *(float4*)(o + c0) = r0;
    *(float4*)(o + c1) = r1;
}

// ===================== TF32 tensor-core GEMM: 128x128x32, cp.async 2-stage =====
#define AS_STRIDE 36
#define BS_STRIDE 136
#define AS_FLOATS (128 * AS_STRIDE)
#define BS_FLOATS (32 * BS_STRIDE)
#define STAGE_FLOATS (AS_FLOATS + BS_FLOATS)
#define GEMM_SMEM (2 * STAGE_FLOATS * 4)

__device__ __forceinline__ void gemm_load_tile(
    const float* __restrict__ A, const float* __restrict__ B,
    int K, int N, int m0, int n0, int k0, unsigned sbase, int tid)
{
    int ar = tid >> 1, ac = (tid & 1) * 16;
    const float* ap = A + (size_t)(m0 + ar) * K + k0 + ac;
    unsigned ad = sbase + (unsigned)(ar * AS_STRIDE + ac) * 4u;
    #pragma unroll
    for (int j = 0; j < 4; ++j) CP_ASYNC16(ad + j * 16, ap + j * 4);

    int br = tid >> 3, bc = (tid & 7) * 16;
    const float* bp = B + (size_t)(k0 + br) * N + n0 + bc;
    unsigned bd = sbase + (unsigned)AS_FLOATS * 4u + (unsigned)(br * BS_STRIDE + bc) * 4u;
    #pragma unroll
    for (int j = 0; j < 4; ++j) CP_ASYNC16(bd + j * 16, bp + j * 4);
}

__global__ __launch_bounds__(256) void sgemm_tf32(
    const float* __restrict__ A, const float* __restrict__ B,
    const float* __restrict__ R, float* __restrict__ C,
    int M, int N, int K)
{
    extern __shared__ float sm[];
    unsigned sbase = (unsigned)__cvta_generic_to_shared(sm);

    int tid = threadIdx.x;
    int wid = tid >> 5, lane = tid & 31;
    int g = lane >> 2, tig = lane & 3;
    int warp_m = wid & 1, warp_n = wid >> 1;
    int m0 = blockIdx.y * 128, n0 = blockIdx.x * 128;
    int am = warp_m * 64, bn = warp_n * 32;

    float acc[4][4][4];
    #pragma unroll
    for (int i = 0; i < 4; ++i)
        #pragma unroll
        for (int j = 0; j < 4; ++j)
            #pragma unroll
            for (int r = 0; r < 4; ++r) acc[i][j][r] = 0.f;

    const int NT = K / 32;
    gemm_load_tile(A, B, K, N, m0, n0, 0, sbase, tid);
    CP_COMMIT();

    int buf = 0;
    for (int kt = 0; kt < NT; ++kt) {
        if (kt + 1 < NT) {
            gemm_load_tile(A, B, K, N, m0, n0, (kt + 1) * 32,
                           sbase + (unsigned)((buf ^ 1) * STAGE_FLOATS * 4), tid);
            CP_COMMIT();
            asm volatile("cp.async.wait_group 1;");
        } else {
            asm volatile("cp.async.wait_group 0;");
        }
        __syncthreads();

        const float* As = sm + buf * STAGE_FLOATS;
        const float* Bs = As + AS_FLOATS;

        #pragma unroll
        for (int s = 0; s < 4; ++s) {
            int ks = s * 8;
            unsigned a[4][4], bfr[4][2];
            #pragma unroll
            for (int i = 0; i < 4; ++i) {
                const float* p = As + (am + i * 16 + g) * AS_STRIDE + ks + tig;
                a[i][0] = __float_as_uint(p[0]);
                a[i][1] = __float_as_uint(p[8 * AS_STRIDE]);
                a[i][2] = __float_as_uint(p[4]);
                a[i][3] = __float_as_uint(p[8 * AS_STRIDE + 4]);
            }
            #pragma unroll
            for (int j = 0; j < 4; ++j) {
                const float* p = Bs + (ks + tig) * BS_STRIDE + bn + j * 8 + g;
                bfr[j][0] = __float_as_uint(p[0]);
                bfr[j][1] = __float_as_uint(p[4 * BS_STRIDE]);
            }
            #pragma unroll
            for (int i = 0; i < 4; ++i)
                #pragma unroll
                for (int j = 0; j < 4; ++j)
                    mma_tf32(acc[i][j], a[i], bfr[j]);
        }
        __syncthreads();
        buf ^= 1;
    }

    #pragma unroll
    for (int i = 0; i < 4; ++i) {
        int row0 = m0 + am + i * 16 + g;
        #pragma unroll
        for (int j = 0; j < 4; ++j) {
            int col = n0 + bn + j * 8 + 2 * tig;
            size_t idx0 = (size_t)row0 * N + col;
            size_t idx1 = idx0 + (size_t)8 * N;
            float2 o0 = make_float2(acc[i][j][0], acc[i][j][1]);
            float2 o1 = make_float2(acc[i][j][2], acc[i][j][3]);
            if (R) {
                float2 r0 = *(const float2*)(R + idx0);
                float2 r1 = *(const float2*)(R + idx1);
                o0.x += r0.x; o0.y += r0.y;
                o1.x += r1.x; o1.y += r1.y;
            }
            *(float2*)(C + idx0) = o0;
            *(float2*)(C + idx1) = o1;
        }
    }
}

// ===================== RoPE + tf32 rounding of Q, K, V =====================
// Thread (b,s,h,i<32): rotates (2i,2i+1) of Q,K; rounds pass-through halves
// (64+2i, 64+2i+1) of Q,K; rounds V[4i..4i+3]. Everything the attention mma
// consumes becomes tf32-rna (avoids RZ truncation bias inside mma).
__global__ __launch_bounds__(256) void rope_kernel(float* __restrict__ qkv)
{
    int t = blockIdx.x * blockDim.x + threadIdx.x;
    int i = t & 31;
    int h = (t >> 5) & 15;
    int s = (t >> 9) & 2047;
    int b = t >> 20;
    if (b >= B_SZ) return;

    size_t base = ((size_t)(b * S_LEN + s)) * D3 + h * DH;
    double th = (double)s * pow(10000.0, -(double)i / 32.0);
    float c = (float)cos(th), sn = (float)sin(th);

    float* q = qkv + base + 2 * i;
    float x1 = q[0], x2 = q[1];
    q[0] = tf32r(x1 * c - x2 * sn);
    q[1] = tf32r(x2 * c + x1 * sn);

    float* k = qkv + base + D_MODEL + 2 * i;
    x1 = k[0]; x2 = k[1];
    k[0] = tf32r(x1 * c - x2 * sn);
    k[1] = tf32r(x2 * c + x1 * sn);

    float* qp = qkv + base + 64 + 2 * i;
    qp[0] = tf32r(qp[0]); qp[1] = tf32r(qp[1]);
    float* kp = qkv + base + D_MODEL + 64 + 2 * i;
    kp[0] = tf32r(kp[0]); kp[1] = tf32r(kp[1]);

    float* v = qkv + base + 2 * D_MODEL + 4 * i;
    float4 vv = *(float4*)v;
    vv.x = tf32r(vv.x); vv.y = tf32r(vv.y);
    vv.z = tf32r(vv.z); vv.w = tf32r(vv.w);
    *(float4*)v = vv;
}

// ===================== TF32 flash attention: BQ=64, BK=32, Dh=128 =============
// 8 warps: warp grid 4(m) x 2(n). S-mma warp tile 16x16; PV warp tile 16x64.
#define QS_ST 132   // ≡4 mod 32: a/b-frag banks 4g+tig conflict-free
#define KS_ST 132
#define VS_ST 136   // ≡8 mod 32: b-frag banks 8tig+g conflict-free
#define SS_ST 36    // ≡4 mod 32
#define QS_FL (64 * QS_ST)          // 8448
#define KS_FL (32 * KS_ST)          // 4224 per buffer (x2)
#define VS_FL (32 * VS_ST)          // 4352
#define SS_FL (64 * SS_ST)          // 2304
#define ATTN_SMEM ((QS_FL + 2 * KS_FL + VS_FL + SS_FL + 192) * 4)

__global__ __launch_bounds__(256) void attn_kernel(
    const float* __restrict__ qkv, float* __restrict__ ctx)
{
    extern __shared__ float sm[];
    float* Qs = sm;
    float* Ks = Qs + QS_FL;            // 2 buffers
    float* Vs = Ks + 2 * KS_FL;
    float* Ss = Vs + VS_FL;
    float* rm = Ss + SS_FL;            // 64
    float* rl = rm + 64;               // 64
    float* rc = rl + 64;               // 64
    unsigned sb = (unsigned)__cvta_generic_to_shared(sm);
    const unsigned KS_OFF = QS_FL * 4u;
    const unsigned VS_OFF = (QS_FL + 2 * KS_FL) * 4u;

    int qt = blockIdx.x, h = blockIdx.y, b = blockIdx.z;
    int tid = threadIdx.x;
    int wid = tid >> 5, lane = tid & 31;
    int g = lane >> 2, tig = lane & 3;
    int wm = wid & 3, wn = wid >> 2;
    int q0 = qt * 64;
    const float SCALE = 0.0883883476483184f;  // 1/sqrt(128)

    // Q tile (64x128) via cp.async
    const float* qbase = qkv + ((size_t)(b * S_LEN + q0)) * D3 + h * DH;
    #pragma unroll
    for (int it = 0; it < 8; ++it) {
        int idx = tid + it * 256;
        int r = idx >> 5, d = (idx & 31) * 4;
        CP_ASYNC16(sb + (unsigned)(r * QS_ST + d) * 4u, qbase + (size_t)r * D3 + d);
    }
    CP_COMMIT();
    // K(0)
    {
        const float* kb = qkv + ((size_t)(b * S_LEN)) * D3 + D_MODEL + h * DH;
        #pragma unroll
        for (int it = 0; it < 4; ++it) {
            int idx = tid + it * 256;
            int r = idx >> 5, d = (idx & 31) * 4;
            CP_ASYNC16(sb + KS_OFF + (unsigned)(r * KS_ST + d) * 4u, kb + (size_t)r * D3 + d);
        }
    }
    CP_COMMIT();
    if (tid < 64) { rm[tid] = -1e30f; rl[tid] = 0.f; }

    float oacc[8][4];
    #pragma unroll
    for (int i = 0; i < 8; ++i)
        #pragma unroll
        for (int r = 0; r < 4; ++r) oacc[i][r] = 0.f;

    asm volatile("cp.async.wait_group 0;");
    __syncthreads();

    int buf = 0;
    for (int kt = 0; kt < S_LEN / 32; ++kt) {
        // issue V(kt)  [group V]
        {
            const float* vb = qkv + ((size_t)(b * S_LEN + kt * 32)) * D3 + 2 * D_MODEL + h * DH;
            #pragma unroll
            for (int it = 0; it < 4; ++it) {
                int idx = tid + it * 256;
                int r = idx >> 5, d = (idx & 31) * 4;
                CP_ASYNC16(sb + VS_OFF + (unsigned)(r * VS_ST + d) * 4u, vb + (size_t)r * D3 + d);
            }
        }
        CP_COMMIT();

        // ---- S = Q * K^T (warp tile 16x16) ----
        float sc[2][4];
        #pragma unroll
        for (int j = 0; j < 2; ++j)
            #pragma unroll
            for (int r = 0; r < 4; ++r) sc[j][r] = 0.f;
        {
            const float* Kb = Ks + buf * KS_FL;
            #pragma unroll
            for (int s = 0; s < 16; ++s) {
                int ks = s * 8;
                unsigned a[4];
                const float* p = Qs + (wm * 16 + g) * QS_ST + ks + tig;
                a[0] = __float_as_uint(p[0]);
                a[1] = __float_as_uint(p[8 * QS_ST]);
                a[2] = __float_as_uint(p[4]);
                a[3] = __float_as_uint(p[8 * QS_ST + 4]);
                #pragma unroll
                for (int j = 0; j < 2; ++j) {
                    const float* kp = Kb + (wn * 16 + 8 * j + g) * KS_ST + ks + tig;
                    unsigned bf[2] = { __float_as_uint(kp[0]), __float_as_uint(kp[4]) };
                    mma_tf32(sc[j], a, bf);
                }
            }
        }
        #pragma unroll
        for (int j = 0; j < 2; ++j) {
            int row = wm * 16 + g;
            int col = wn * 16 + 8 * j + 2 * tig;
            Ss[row * SS_ST + col]           = sc[j][0] * SCALE;
            Ss[row * SS_ST + col + 1]       = sc[j][1] * SCALE;
            Ss[(row + 8) * SS_ST + col]     = sc[j][2] * SCALE;
            Ss[(row + 8) * SS_ST + col + 1] = sc[j][3] * SCALE;
        }

        // issue K(kt+1)  [group K]
        if (kt + 1 < S_LEN / 32) {
            const float* kb = qkv + ((size_t)(b * S_LEN + (kt + 1) * 32)) * D3 + D_MODEL + h * DH;
            unsigned kd = KS_OFF + (unsigned)((buf ^ 1) * KS_FL) * 4u;
            #pragma unroll
            for (int it = 0; it < 4; ++it) {
                int idx = tid + it * 256;
                int r = idx >> 5, d = (idx & 31) * 4;
                CP_ASYNC16(sb + kd + (unsigned)(r * KS_ST + d) * 4u, kb + (size_t)r * D3 + d);
            }
        }
        CP_COMMIT();
        __syncthreads();   // S tiles visible to softmax warps

        // ---- online softmax: warp wid owns rows 8*wid..8*wid+7, col = lane ----
        #pragma unroll
        for (int rr = 0; rr < 8; ++rr) {
            int r = 8 * wid + rr;
            float v = Ss[r * SS_ST + lane];
            float mx = v;
            #pragma unroll
            for (int off = 16; off; off >>= 1)
                mx = fmaxf(mx, __shfl_xor_sync(0xffffffffu, mx, off));
            float m_old = rm[r];
            float m_new = fmaxf(m_old, mx);
            float p = __expf(v - m_new);
            Ss[r * SS_ST + lane] = tf32r(p);
            float su = p;
            #pragma unroll
            for (int off = 16; off; off >>= 1)
                su += __shfl_xor_sync(0xffffffffu, su, off);
            if (lane == 0) {
                float corr = __expf(m_old - m_new);
                rc[r] = corr;
                rl[r] = rl[r] * corr + su;
                rm[r] = m_new;
            }
        }

        asm volatile("cp.async.wait_group 1;");  // V(kt) landed (K(kt+1) may pend)
        __syncthreads();                          // P + rc visible; Vs ready

        // ---- rescale O, then O += P * V (warp tile 16x64) ----
        {
            float c0 = rc[wm * 16 + g];
            float c1 = rc[wm * 16 + 8 + g];
            #pragma unroll
            for (int jn = 0; jn < 8; ++jn) {
                oacc[jn][0] *= c0; oacc[jn][1] *= c0;
                oacc[jn][2] *= c1; oacc[jn][3] *= c1;
            }
        }
        #pragma unroll
        for (int s = 0; s < 4; ++s) {
            int ks = s * 8;
            unsigned a[4];
            const float* p = Ss + (wm * 16 + g) * SS_ST + ks + tig;
            a[0] = __float_as_uint(p[0]);
            a[1] = __float_as_uint(p[8 * SS_ST]);
            a[2] = __float_as_uint(p[4]);
            a[3] = __float_as_uint(p[8 * SS_ST + 4]);
            #pragma unroll
            for (int jn = 0; jn < 8; ++jn) {
                const float* vp = Vs + (ks + tig) * VS_ST + wn * 64 + 8 * jn + g;
                unsigned bf[2] = { __float_as_uint(vp[0]), __float_as_uint(vp[4 * VS_ST]) };
                mma_tf32(oacc[jn], a, bf);
            }
        }
        asm volatile("cp.async.wait_group 0;");  // K(kt+1) landed
        __syncthreads();                          // Ss/Vs free for next iter
        buf ^= 1;
    }

    // ---- epilogue: O /= l, tf32-round (feeds TF32 out-projection) ----
    float inv0 = 1.0f / rl[wm * 16 + g];
    float inv1 = 1.0f / rl[wm * 16 + 8 + g];
    #pragma unroll
    for (int jn = 0; jn < 8; ++jn) {
        int col = h * DH + wn * 64 + 8 * jn + 2 * tig;
        size_t i0 = ((size_t)(b * S_LEN + q0 + wm * 16 + g)) * D_MODEL + col;
        size_t i1 = i0 + (size_t)8 * D_MODEL;
        float2 o0 = make_float2(tf32r(oacc[jn][0] * inv0), tf32r(oacc[jn][1] * inv0));
        float2 o1 = make_float2(tf32r(oacc[jn][2] * inv1), tf32r(oacc[jn][3] * inv1));
        *(float2*)(ctx + i0) = o0;
        *(float2*)(ctx + i1) = o1;
    }
}

// ===================== launcher =====================
extern "C" void kernel_launch(void* const* d_in, const int* in_sizes, int n_in,
                              void* d_out, int out_size)
{
    const float* X     = (const float*)d_in[0];
    const float* ln_w  = (const float*)d_in[1];
    const float* ln_b  = (const float*)d_in[2];
    const float* W_in  = (const float*)d_in[3];
    const float* W_out = (const float*)d_in[4];
    float* out = (float*)d_out;

    float *xn, *qkv, *ctx, *win, *wout;
    cudaGetSymbolAddress((void**)&xn,   g_xn);
    cudaGetSymbolAddress((void**)&qkv,  g_qkv);
    cudaGetSymbolAddress((void**)&ctx,  g_ctx);
    cudaGetSymbolAddress((void**)&win,  g_win);
    cudaGetSymbolAddress((void**)&wout, g_wout);

    {
        int n1 = D_MODEL * D3;
        int n2 = D_MODEL * D_MODEL;
        wcvt_kernel<<<n1 / 1024, 256>>>(W_in,  win,  n1);
        wcvt_kernel<<<n2 / 1024, 256>>>(W_out, wout, n2);
    }

    ln_kernel<<<NTOK, 256>>>(X, ln_w, ln_b, xn);

    cudaFuncSetAttribute(sgemm_tf32, cudaFuncAttributeMaxDynamicSharedMemorySize, GEMM_SMEM);

    dim3 g1(D3 / 128, NTOK / 128);
    sgemm_tf32<<<g1, 256, GEMM_SMEM>>>(xn, win, nullptr, qkv, NTOK, D3, D_MODEL);

    rope_kernel<<<(B_SZ * S_LEN * H_NUM * 32) / 256, 256>>>(qkv);

    cudaFuncSetAttribute(attn_kernel, cudaFuncAttributeMaxDynamicSharedMemorySize, ATTN_SMEM);
    attn_kernel<<<dim3(S_LEN / 64, H_NUM, B_SZ), 256, ATTN_SMEM>>>(qkv, ctx);

    dim3 g2(D_MODEL / 128, NTOK / 128);
    sgemm_tf32<<<g2, 256, GEMM_SMEM>>>(ctx, wout, X, out, NTOK, D_MODEL, D_MODEL);
}

// round 9
// speedup vs baseline: 3.5545x; 1.7745x over previous
#include <cuda_runtime.h>
#include <cuda_bf16.h>
#include <math.h>

#define B_SZ 4
#define S_LEN 2048
#define D_MODEL 2048
#define H_NUM 16
#define DH 128
#define D3 6144
#define NTOK (B_SZ * S_LEN)   // 8192

// -------- scratch (allocation-free rule: __device__ globals) --------
__device__ __nv_bfloat16 g_xn  [(size_t)NTOK * D_MODEL];     // 32 MB
__device__ __nv_bfloat16 g_qkv [(size_t)NTOK * D3];          // 100 MB
__device__ __nv_bfloat16 g_ctx [(size_t)NTOK * D_MODEL];     // 32 MB
__device__ __nv_bfloat16 g_win [(size_t)D_MODEL * D3];       // 24 MB
__device__ __nv_bfloat16 g_wout[(size_t)D_MODEL * D_MODEL];  // 8 MB

// ---------- helpers ----------
#define CP_ASYNC16(dst, src) \
    asm volatile("cp.async.cg.shared.global [%0], [%1], 16;" :: "r"(dst), "l"(src))
#define CP_COMMIT() asm volatile("cp.async.commit_group;")

#define LDM_X4(r0, r1, r2, r3, addr) \
    asm volatile("ldmatrix.sync.aligned.m8n8.x4.shared.b16 {%0,%1,%2,%3}, [%4];" \
        : "=r"(r0), "=r"(r1), "=r"(r2), "=r"(r3) : "r"(addr))
#define LDM_X4_T(r0, r1, r2, r3, addr) \
    asm volatile("ldmatrix.sync.aligned.m8n8.x4.trans.shared.b16 {%0,%1,%2,%3}, [%4];" \
        : "=r"(r0), "=r"(r1), "=r"(r2), "=r"(r3) : "r"(addr))

__device__ __forceinline__ void mma_bf16(float* c, const unsigned* a, const unsigned* b) {
    asm volatile(
        "mma.sync.aligned.m16n8k16.row.col.f32.bf16.bf16.f32 "
        "{%0,%1,%2,%3}, {%4,%5,%6,%7}, {%8,%9}, {%0,%1,%2,%3};"
        : "+f"(c[0]), "+f"(c[1]), "+f"(c[2]), "+f"(c[3])
        : "r"(a[0]), "r"(a[1]), "r"(a[2]), "r"(a[3]), "r"(b[0]), "r"(b[1]));
}

__device__ __forceinline__ unsigned pack_bf16x2(float lo, float hi) {
    unsigned r;
    asm("cvt.rn.bf16x2.f32 %0, %1, %2;" : "=r"(r) : "f"(hi), "f"(lo));
    return r;
}

// ===================== weight fp32 -> bf16 =====================
__global__ __launch_bounds__(256) void wcvt_kernel(
    const float* __restrict__ in, __nv_bfloat16* __restrict__ out, int n)
{
    int i = (blockIdx.x * 256 + threadIdx.x) * 8;
    if (i >= n) return;
    float4 v0 = *(const float4*)(in + i);
    float4 v1 = *(const float4*)(in + i + 4);
    uint4 o;
    o.x = pack_bf16x2(v0.x, v0.y);
    o.y = pack_bf16x2(v0.z, v0.w);
    o.z = pack_bf16x2(v1.x, v1.y);
    o.w = pack_bf16x2(v1.z, v1.w);
    *(uint4*)(out + i) = o;
}

// ===================== LayerNorm (bf16 output) =====================
__global__ __launch_bounds__(256) void ln_kernel(
    const float* __restrict__ X, const float* __restrict__ w,
    const float* __restrict__ b, __nv_bfloat16* __restrict__ out)
{
    int row = blockIdx.x;
    int t = threadIdx.x;
    int lane = t & 31, wrp = t >> 5;
    const float* x = X + (size_t)row * D_MODEL;

    float4 v0 = *(const float4*)(x + t * 4);
    float4 v1 = *(const float4*)(x + 1024 + t * 4);

    float s  = v0.x + v0.y + v0.z + v0.w + v1.x + v1.y + v1.z + v1.w;
    float sq = v0.x*v0.x + v0.y*v0.y + v0.z*v0.z + v0.w*v0.w
             + v1.x*v1.x + v1.y*v1.y + v1.z*v1.z + v1.w*v1.w;

    #pragma unroll
    for (int off = 16; off; off >>= 1) {
        s  += __shfl_xor_sync(0xffffffffu, s,  off);
        sq += __shfl_xor_sync(0xffffffffu, sq, off);
    }
    __shared__ float sh_s[8], sh_q[8];
    if (lane == 0) { sh_s[wrp] = s; sh_q[wrp] = sq; }
    __syncthreads();
    float tot = 0.f, totq = 0.f;
    #pragma unroll
    for (int i = 0; i < 8; ++i) { tot += sh_s[i]; totq += sh_q[i]; }
    float mean = tot * (1.0f / D_MODEL);
    float var  = totq * (1.0f / D_MODEL) - mean * mean;
    float inv  = rsqrtf(var + 1e-5f);

    __nv_bfloat16* o = out + (size_t)row * D_MODEL;
    int c0 = t * 4, c1 = 1024 + t * 4;
    float4 w0 = *(const float4*)(w + c0), w1 = *(const float4*)(w + c1);
    float4 b0 = *(const float4*)(b + c0), b1 = *(const float4*)(b + c1);
    uint2 p0, p1;
    p0.x = pack_bf16x2((v0.x - mean) * inv * w0.x + b0.x,
                       (v0.y - mean) * inv * w0.y + b0.y);
    p0.y = pack_bf16x2((v0.z - mean) * inv * w0.z + b0.z,
                       (v0.w - mean) * inv * w0.w + b0.w);
    p1.x = pack_bf16x2((v1.x - mean) * inv * w1.x + b1.x,
                       (v1.y - mean) * inv * w1.y + b1.y);
    p1.y = pack_bf16x2((v1.z - mean) * inv * w1.z + b1.z,
                       (v1.w - mean) * inv * w1.w + b1.w);
    *(uint2*)(o + c0) = p0;
    *(uint2*)(o + c1) = p1;
}

// ===================== BF16 tensor-core GEMM: 128x128x32, 3-stage ============
// A: MxK row-major bf16, B: KxN row-major bf16. Cb!=null -> bf16 out;
// else fp32 out (+R residual). 256 thr, warps 2(m)x4(n), warp tile 64x32.
#define GAST 40                         // A smem stride (bf16): 80 B/row (80/16=5 odd)
#define GBST 136                        // B smem stride: 272 B/row (272/16=17 odd)
#define GA_BYTES (128 * GAST * 2)       // 10240
#define GB_BYTES (32 * GBST * 2)        // 8704
#define GSTAGE (GA_BYTES + GB_BYTES)    // 18944
#define GEMM_SMEM (3 * GSTAGE)          // 56832

__device__ __forceinline__ void gemm_load_tile(
    const __nv_bfloat16* __restrict__ A, const __nv_bfloat16* __restrict__ B,
    int K, int N, int m0, int n0, int k0, unsigned stg, int tid)
{
    #pragma unroll
    for (int i = 0; i < 2; ++i) {
        int id = tid + i * 256;
        int r = id >> 2, c = id & 3;          // A: 128 rows x 4 chunks
        CP_ASYNC16(stg + (unsigned)(r * 80 + c * 16),
                   A + (size_t)(m0 + r) * K + k0 + c * 8);
    }
    #pragma unroll
    for (int i = 0; i < 2; ++i) {
        int id = tid + i * 256;
        int r = id >> 4, c = id & 15;         // B: 32 rows x 16 chunks
        CP_ASYNC16(stg + (unsigned)GA_BYTES + (unsigned)(r * 272 + c * 16),
                   B + (size_t)(k0 + r) * N + n0 + c * 8);
    }
}

__global__ __launch_bounds__(256) void gemm_bf16(
    const __nv_bfloat16* __restrict__ A, const __nv_bfloat16* __restrict__ B,
    const float* __restrict__ R, float* __restrict__ Cf,
    __nv_bfloat16* __restrict__ Cb, int M, int N, int K)
{
    extern __shared__ char smc[];
    unsigned sb = (unsigned)__cvta_generic_to_shared(smc);

    int tid = threadIdx.x;
    int wid = tid >> 5, lane = tid & 31;
    int g = lane >> 2, tig = lane & 3;
    int wm = wid & 1, wn = wid >> 1;
    int m0 = blockIdx.y * 128, n0 = blockIdx.x * 128;
    int am = wm * 64, bn = wn * 32;

    float acc[4][4][4];
    #pragma unroll
    for (int i = 0; i < 4; ++i)
        #pragma unroll
        for (int j = 0; j < 4; ++j)
            #pragma unroll
            for (int r = 0; r < 4; ++r) acc[i][j][r] = 0.f;

    const int NT = K / 32;
    gemm_load_tile(A, B, K, N, m0, n0, 0, sb, tid);
    CP_COMMIT();
    gemm_load_tile(A, B, K, N, m0, n0, 32, sb + GSTAGE, tid);
    CP_COMMIT();

    int lrow = lane & 15, lhi = lane >> 4;   // ldmatrix lane decomposition

    for (int kt = 0; kt < NT; ++kt) {
        if (kt + 1 < NT) asm volatile("cp.async.wait_group 1;");
        else             asm volatile("cp.async.wait_group 0;");
        __syncthreads();

        if (kt + 2 < NT) {
            gemm_load_tile(A, B, K, N, m0, n0, (kt + 2) * 32,
                           sb + (unsigned)(((kt + 2) % 3) * GSTAGE), tid);
            CP_COMMIT();
        }

        unsigned sA = sb + (unsigned)((kt % 3) * GSTAGE);
        unsigned sB = sA + (unsigned)GA_BYTES;

        #pragma unroll
        for (int s = 0; s < 2; ++s) {
            int ksb = s * 32;   // byte offset of k-step (16 bf16)
            unsigned a[4][4];
            #pragma unroll
            for (int i = 0; i < 4; ++i)
                LDM_X4(a[i][0], a[i][1], a[i][2], a[i][3],
                       sA + (unsigned)((am + i * 16 + lrow) * 80 + ksb + lhi * 16));
            unsigned bf[4][2];
            #pragma unroll
            for (int jp = 0; jp < 2; ++jp) {
                unsigned t0, t1, t2, t3;
                LDM_X4_T(t0, t1, t2, t3,
                         sB + (unsigned)((s * 16 + lrow) * 272 +
                                         (bn + jp * 16 + lhi * 8) * 2));
                bf[2 * jp][0] = t0; bf[2 * jp][1] = t1;
                bf[2 * jp + 1][0] = t2; bf[2 * jp + 1][1] = t3;
            }
            #pragma unroll
            for (int i = 0; i < 4; ++i)
                #pragma unroll
                for (int j = 0; j < 4; ++j)
                    mma_bf16(acc[i][j], a[i], bf[j]);
        }
        __syncthreads();
    }

    #pragma unroll
    for (int i = 0; i < 4; ++i) {
        int row0 = m0 + am + i * 16 + g;
        #pragma unroll
        for (int j = 0; j < 4; ++j) {
            int col = n0 + bn + j * 8 + 2 * tig;
            size_t idx0 = (size_t)row0 * N + col;
            size_t idx1 = idx0 + (size_t)8 * N;
            if (Cb) {
                *(unsigned*)(Cb + idx0) = pack_bf16x2(acc[i][j][0], acc[i][j][1]);
                *(unsigned*)(Cb + idx1) = pack_bf16x2(acc[i][j][2], acc[i][j][3]);
            } else {
                float2 o0 = make_float2(acc[i][j][0], acc[i][j][1]);
                float2 o1 = make_float2(acc[i][j][2], acc[i][j][3]);
                float2 r0 = *(const float2*)(R + idx0);
                float2 r1 = *(const float2*)(R + idx1);
                o0.x += r0.x; o0.y += r0.y;
                o1.x += r1.x; o1.y += r1.y;
                *(float2*)(Cf + idx0) = o0;
                *(float2*)(Cf + idx1) = o1;
            }
        }
    }
}

// ===================== RoPE in place on bf16 qkv (Q,K first 64 chans) =========
__global__ __launch_bounds__(256) void rope_kernel(__nv_bfloat16* __restrict__ qkv)
{
    int t = blockIdx.x * blockDim.x + threadIdx.x;
    int i = t & 31;
    int h = (t >> 5) & 15;
    int s = (t >> 9) & 2047;
    int b = t >> 20;
    if (b >= B_SZ) return;

    size_t base = ((size_t)(b * S_LEN + s)) * D3 + h * DH;
    double th = (double)s * pow(10000.0, -(double)i / 32.0);
    float c = (float)cos(th), sn = (float)sin(th);

    __nv_bfloat162* q = (__nv_bfloat162*)(qkv + base + 2 * i);
    float x1 = __bfloat162float(q->x), x2 = __bfloat162float(q->y);
    *q = __floats2bfloat162_rn(x1 * c - x2 * sn, x2 * c + x1 * sn);

    __nv_bfloat162* k = (__nv_bfloat162*)(qkv + base + D_MODEL + 2 * i);
    x1 = __bfloat162float(k->x); x2 = __bfloat162float(k->y);
    *k = __floats2bfloat162_rn(x1 * c - x2 * sn, x2 * c + x1 * sn);
}

// ===================== BF16 flash attention: BQ=64, BK=32, Dh=128 =============
// 8 warps: 4(m) x 2(n). S warp tile 16x16; PV warp tile 16x64.
// smem byte layout (strides: rows 272 B = 17*16 -> ldmatrix conflict-free;
// Ps rows 80 B = 5*16):
#define AQS_B 0u                       // Q: 64 x 136 bf16
#define AKS_B 17408u                   // K: 2 x (32 x 136) bf16
#define AVS_B 34816u                   // V: 32 x 136 bf16
#define ASS_B 43520u                   // S: 64 x 36 fp32
#define APS_B 52736u                   // P: 64 x 40 bf16
#define ARM_B 57856u                   // rm/rl/rc: 3 x 64 fp32
#define ATTN_SMEM 58624
#define ASS_ST 36

__global__ __launch_bounds__(256) void attn_kernel(
    const __nv_bfloat16* __restrict__ qkv, __nv_bfloat16* __restrict__ ctx)
{
    extern __shared__ char smc[];
    unsigned sb = (unsigned)__cvta_generic_to_shared(smc);
    float* Ss = (float*)(smc + ASS_B);
    __nv_bfloat16* Ps = (__nv_bfloat16*)(smc + APS_B);
    float* rm = (float*)(smc + ARM_B);
    float* rl = rm + 64;
    float* rc = rl + 64;

    int qt = blockIdx.x, h = blockIdx.y, b = blockIdx.z;
    int tid = threadIdx.x;
    int wid = tid >> 5, lane = tid & 31;
    int g = lane >> 2, tig = lane & 3;
    int lrow = lane & 15, lhi = lane >> 4;
    int wm = wid & 3, wn = wid >> 2;
    int q0 = qt * 64;
    const float SCALE = 0.0883883476483184f;  // 1/sqrt(128)

    // Q tile (64 x 128 bf16): 1024 chunks of 16B
    const __nv_bfloat16* qbase = qkv + ((size_t)(b * S_LEN + q0)) * D3 + h * DH;
    #pragma unroll
    for (int it = 0; it < 4; ++it) {
        int id = tid + it * 256;
        int r = id >> 4, c = id & 15;
        CP_ASYNC16(sb + AQS_B + (unsigned)(r * 272 + c * 16),
                   qbase + (size_t)r * D3 + c * 8);
    }
    CP_COMMIT();
    // K(0): 512 chunks
    {
        const __nv_bfloat16* kb = qkv + ((size_t)(b * S_LEN)) * D3 + D_MODEL + h * DH;
        #pragma unroll
        for (int it = 0; it < 2; ++it) {
            int id = tid + it * 256;
            int r = id >> 4, c = id & 15;
            CP_ASYNC16(sb + AKS_B + (unsigned)(r * 272 + c * 16),
                       kb + (size_t)r * D3 + c * 8);
        }
    }
    CP_COMMIT();
    if (tid < 64) { rm[tid] = -1e30f; rl[tid] = 0.f; }

    float oacc[8][4];
    #pragma unroll
    for (int i = 0; i < 8; ++i)
        #pragma unroll
        for (int r = 0; r < 4; ++r) oacc[i][r] = 0.f;

    asm volatile("cp.async.wait_group 0;");
    __syncthreads();

    int buf = 0;
    for (int kt = 0; kt < S_LEN / 32; ++kt) {
        // issue V(kt)
        {
            const __nv_bfloat16* vb = qkv + ((size_t)(b * S_LEN + kt * 32)) * D3
                                      + 2 * D_MODEL + h * DH;
            #pragma unroll
            for (int it = 0; it < 2; ++it) {
                int id = tid + it * 256;
                int r = id >> 4, c = id & 15;
                CP_ASYNC16(sb + AVS_B + (unsigned)(r * 272 + c * 16),
                           vb + (size_t)r * D3 + c * 8);
            }
        }
        CP_COMMIT();

        // ---- S = Q K^T: warp tile 16(m) x 16(n), 8 k-steps of 16 ----
        float sc[2][4];
        #pragma unroll
        for (int j = 0; j < 2; ++j)
            #pragma unroll
            for (int r = 0; r < 4; ++r) sc[j][r] = 0.f;
        {
            unsigned sK = sb + AKS_B + (unsigned)(buf * (32 * 272));
            unsigned sQ = sb + AQS_B;
            #pragma unroll
            for (int s = 0; s < 8; s += 2) {
                // A: two k-steps worth of Q frags
                unsigned a0[4], a1[4];
                LDM_X4(a0[0], a0[1], a0[2], a0[3],
                       sQ + (unsigned)((wm * 16 + lrow) * 272 + s * 32 + lhi * 16));
                LDM_X4(a1[0], a1[1], a1[2], a1[3],
                       sQ + (unsigned)((wm * 16 + lrow) * 272 + (s + 1) * 32 + lhi * 16));
                #pragma unroll
                for (int j = 0; j < 2; ++j) {
                    // K b-frags (non-trans): 8 key-rows, 2 k-steps per x4
                    unsigned t0, t1, t2, t3;
                    LDM_X4(t0, t1, t2, t3,
                           sK + (unsigned)((wn * 16 + j * 8 + (lane & 7)) * 272 +
                                           s * 32 + (lane >> 3) * 16));
                    unsigned b0[2] = { t0, t1 }, b1[2] = { t2, t3 };
                    mma_bf16(sc[j], a0, b0);
                    mma_bf16(sc[j], a1, b1);
                }
            }
        }
        #pragma unroll
        for (int j = 0; j < 2; ++j) {
            int row = wm * 16 + g;
            int col = wn * 16 + 8 * j + 2 * tig;
            Ss[row * ASS_ST + col]           = sc[j][0] * SCALE;
            Ss[row * ASS_ST + col + 1]       = sc[j][1] * SCALE;
            Ss[(row + 8) * ASS_ST + col]     = sc[j][2] * SCALE;
            Ss[(row + 8) * ASS_ST + col + 1] = sc[j][3] * SCALE;
        }

        // issue K(kt+1)
        if (kt + 1 < S_LEN / 32) {
            const __nv_bfloat16* kb = qkv + ((size_t)(b * S_LEN + (kt + 1) * 32)) * D3
                                      + D_MODEL + h * DH;
            unsigned kd = sb + AKS_B + (unsigned)((buf ^ 1) * (32 * 272));
            #pragma unroll
            for (int it = 0; it < 2; ++it) {
                int id = tid + it * 256;
                int r = id >> 4, c = id & 15;
                CP_ASYNC16(kd + (unsigned)(r * 272 + c * 16), kb + (size_t)r * D3 + c * 8);
            }
        }
        CP_COMMIT();
        __syncthreads();   // S visible to softmax warps

        // ---- online softmax: warp wid owns rows 8*wid..8*wid+7, col=lane ----
        #pragma unroll
        for (int rr = 0; rr < 8; ++rr) {
            int r = 8 * wid + rr;
            float v = Ss[r * ASS_ST + lane];
            float mx = v;
            #pragma unroll
            for (int off = 16; off; off >>= 1)
                mx = fmaxf(mx, __shfl_xor_sync(0xffffffffu, mx, off));
            float m_old = rm[r];
            float m_new = fmaxf(m_old, mx);
            float p = __expf(v - m_new);
            Ps[r * 40 + lane] = __float2bfloat16_rn(p);
            float su = p;
            #pragma unroll
            for (int off = 16; off; off >>= 1)
                su += __shfl_xor_sync(0xffffffffu, su, off);
            if (lane == 0) {
                float corr = __expf(m_old - m_new);
                rc[r] = corr;
                rl[r] = rl[r] * corr + su;
                rm[r] = m_new;
            }
        }

        asm volatile("cp.async.wait_group 1;");  // V(kt) landed
        __syncthreads();                          // P + rc visible; Vs ready

        // ---- rescale O; O += P V (warp tile 16 x 64, 2 k-steps) ----
        {
            float c0 = rc[wm * 16 + g];
            float c1 = rc[wm * 16 + 8 + g];
            #pragma unroll
            for (int jn = 0; jn < 8; ++jn) {
                oacc[jn][0] *= c0; oacc[jn][1] *= c0;
                oacc[jn][2] *= c1; oacc[jn][3] *= c1;
            }
        }
        {
            unsigned pa[2][4];
            #pragma unroll
            for (int s = 0; s < 2; ++s)
                LDM_X4(pa[s][0], pa[s][1], pa[s][2], pa[s][3],
                       sb + APS_B + (unsigned)((wm * 16 + lrow) * 80 + s * 32 + lhi * 16));
            #pragma unroll
            for (int jn = 0; jn < 8; ++jn) {
                unsigned t0, t1, t2, t3;   // V trans x4: k rows 0..31, one dh n-frag
                LDM_X4_T(t0, t1, t2, t3,
                         sb + AVS_B + (unsigned)(lane * 272 + (wn * 64 + jn * 8) * 2));
                unsigned b0[2] = { t0, t1 }, b1[2] = { t2, t3 };
                mma_bf16(oacc[jn], pa[0], b0);
                mma_bf16(oacc[jn], pa[1], b1);
            }
        }
        asm volatile("cp.async.wait_group 0;");  // K(kt+1) landed
        __syncthreads();                          // Ss/Ps/Vs free for next iter
        buf ^= 1;
    }

    // ---- epilogue: O /= l, bf16 (feeds BF16 out-projection) ----
    float inv0 = 1.0f / rl[wm * 16 + g];
    float inv1 = 1.0f / rl[wm * 16 + 8 + g];
    #pragma unroll
    for (int jn = 0; jn < 8; ++jn) {
        int col = h * DH + wn * 64 + 8 * jn + 2 * tig;
        size_t i0 = ((size_t)(b * S_LEN + q0 + wm * 16 + g)) * D_MODEL + col;
        size_t i1 = i0 + (size_t)8 * D_MODEL;
        *(unsigned*)(ctx + i0) = pack_bf16x2(oacc[jn][0] * inv0, oacc[jn][1] * inv0);
        *(unsigned*)(ctx + i1) = pack_bf16x2(oacc[jn][2] * inv1, oacc[jn][3] * inv1);
    }
}

// ===================== launcher =====================
extern "C" void kernel_launch(void* const* d_in, const int* in_sizes, int n_in,
                              void* d_out, int out_size)
{
    const float* X     = (const float*)d_in[0];
    const float* ln_w  = (const float*)d_in[1];
    const float* ln_b  = (const float*)d_in[2];
    const float* W_in  = (const float*)d_in[3];
    const float* W_out = (const float*)d_in[4];
    float* out = (float*)d_out;

    __nv_bfloat16 *xn, *qkv, *ctx, *win, *wout;
    cudaGetSymbolAddress((void**)&xn,   g_xn);
    cudaGetSymbolAddress((void**)&qkv,  g_qkv);
    cudaGetSymbolAddress((void**)&ctx,  g_ctx);
    cudaGetSymbolAddress((void**)&win,  g_win);
    cudaGetSymbolAddress((void**)&wout, g_wout);

    {
        int n1 = D_MODEL * D3;       // 12.6M
        int n2 = D_MODEL * D_MODEL;  // 4.2M
        wcvt_kernel<<<n1 / 2048, 256>>>(W_in,  win,  n1);
        wcvt_kernel<<<n2 / 2048, 256>>>(W_out, wout, n2);
    }

    ln_kernel<<<NTOK, 256>>>(X, ln_w, ln_b, xn);

    cudaFuncSetAttribute(gemm_bf16, cudaFuncAttributeMaxDynamicSharedMemorySize, GEMM_SMEM);

    dim3 g1(D3 / 128, NTOK / 128);
    gemm_bf16<<<g1, 256, GEMM_SMEM>>>(xn, win, nullptr, nullptr, qkv, NTOK, D3, D_MODEL);

    rope_kernel<<<(B_SZ * S_LEN * H_NUM * 32) / 256, 256>>>(qkv);

    cudaFuncSetAttribute(attn_kernel, cudaFuncAttributeMaxDynamicSharedMemorySize, ATTN_SMEM);
    attn_kernel<<<dim3(S_LEN / 64, H_NUM, B_SZ), 256, ATTN_SMEM>>>(qkv, ctx);

    dim3 g2(D_MODEL / 128, NTOK / 128);
    gemm_bf16<<<g2, 256, GEMM_SMEM>>>(ctx, wout, X, out, nullptr, NTOK, D_MODEL, D_MODEL);
}

// round 10
// speedup vs baseline: 4.5608x; 1.2831x over previous
#include <cuda_runtime.h>
#include <cuda_bf16.h>
#include <math.h>

#define B_SZ 4
#define S_LEN 2048
#define D_MODEL 2048
#define H_NUM 16
#define DH 128
#define D3 6144
#define NTOK (B_SZ * S_LEN)   // 8192

// -------- scratch (allocation-free rule: __device__ globals) --------
__device__ __nv_bfloat16 g_xn  [(size_t)NTOK * D_MODEL];     // 32 MB
__device__ __nv_bfloat16 g_qkv [(size_t)NTOK * D3];          // 100 MB
__device__ __nv_bfloat16 g_ctx [(size_t)NTOK * D_MODEL];     // 32 MB
__device__ __nv_bfloat16 g_win [(size_t)D_MODEL * D3];       // 24 MB
__device__ __nv_bfloat16 g_wout[(size_t)D_MODEL * D_MODEL];  // 8 MB

// ---------- helpers ----------
#define CP_ASYNC16(dst, src) \
    asm volatile("cp.async.cg.shared.global [%0], [%1], 16;" :: "r"(dst), "l"(src))
#define CP_COMMIT() asm volatile("cp.async.commit_group;")

#define LDM_X4(r0, r1, r2, r3, addr) \
    asm volatile("ldmatrix.sync.aligned.m8n8.x4.shared.b16 {%0,%1,%2,%3}, [%4];" \
        : "=r"(r0), "=r"(r1), "=r"(r2), "=r"(r3) : "r"(addr))
#define LDM_X4_T(r0, r1, r2, r3, addr) \
    asm volatile("ldmatrix.sync.aligned.m8n8.x4.trans.shared.b16 {%0,%1,%2,%3}, [%4];" \
        : "=r"(r0), "=r"(r1), "=r"(r2), "=r"(r3) : "r"(addr))

__device__ __forceinline__ void mma_bf16(float* c, const unsigned* a, const unsigned* b) {
    asm volatile(
        "mma.sync.aligned.m16n8k16.row.col.f32.bf16.bf16.f32 "
        "{%0,%1,%2,%3}, {%4,%5,%6,%7}, {%8,%9}, {%0,%1,%2,%3};"
        : "+f"(c[0]), "+f"(c[1]), "+f"(c[2]), "+f"(c[3])
        : "r"(a[0]), "r"(a[1]), "r"(a[2]), "r"(a[3]), "r"(b[0]), "r"(b[1]));
}

__device__ __forceinline__ unsigned pack_bf16x2(float lo, float hi) {
    unsigned r;
    asm("cvt.rn.bf16x2.f32 %0, %1, %2;" : "=r"(r) : "f"(hi), "f"(lo));
    return r;
}

// ===================== weight fp32 -> bf16 =====================
__global__ __launch_bounds__(256) void wcvt_kernel(
    const float* __restrict__ in, __nv_bfloat16* __restrict__ out, int n)
{
    int i = (blockIdx.x * 256 + threadIdx.x) * 8;
    if (i >= n) return;
    float4 v0 = *(const float4*)(in + i);
    float4 v1 = *(const float4*)(in + i + 4);
    uint4 o;
    o.x = pack_bf16x2(v0.x, v0.y);
    o.y = pack_bf16x2(v0.z, v0.w);
    o.z = pack_bf16x2(v1.x, v1.y);
    o.w = pack_bf16x2(v1.z, v1.w);
    *(uint4*)(out + i) = o;
}

// ===================== LayerNorm (bf16 output) =====================
__global__ __launch_bounds__(256) void ln_kernel(
    const float* __restrict__ X, const float* __restrict__ w,
    const float* __restrict__ b, __nv_bfloat16* __restrict__ out)
{
    int row = blockIdx.x;
    int t = threadIdx.x;
    int lane = t & 31, wrp = t >> 5;
    const float* x = X + (size_t)row * D_MODEL;

    float4 v0 = *(const float4*)(x + t * 4);
    float4 v1 = *(const float4*)(x + 1024 + t * 4);

    float s  = v0.x + v0.y + v0.z + v0.w + v1.x + v1.y + v1.z + v1.w;
    float sq = v0.x*v0.x + v0.y*v0.y + v0.z*v0.z + v0.w*v0.w
             + v1.x*v1.x + v1.y*v1.y + v1.z*v1.z + v1.w*v1.w;

    #pragma unroll
    for (int off = 16; off; off >>= 1) {
        s  += __shfl_xor_sync(0xffffffffu, s,  off);
        sq += __shfl_xor_sync(0xffffffffu, sq, off);
    }
    __shared__ float sh_s[8], sh_q[8];
    if (lane == 0) { sh_s[wrp] = s; sh_q[wrp] = sq; }
    __syncthreads();
    float tot = 0.f, totq = 0.f;
    #pragma unroll
    for (int i = 0; i < 8; ++i) { tot += sh_s[i]; totq += sh_q[i]; }
    float mean = tot * (1.0f / D_MODEL);
    float var  = totq * (1.0f / D_MODEL) - mean * mean;
    float inv  = rsqrtf(var + 1e-5f);

    __nv_bfloat16* o = out + (size_t)row * D_MODEL;
    int c0 = t * 4, c1 = 1024 + t * 4;
    float4 w0 = *(const float4*)(w + c0), w1 = *(const float4*)(w + c1);
    float4 b0 = *(const float4*)(b + c0), b1 = *(const float4*)(b + c1);
    uint2 p0, p1;
    p0.x = pack_bf16x2((v0.x - mean) * inv * w0.x + b0.x,
                       (v0.y - mean) * inv * w0.y + b0.y);
    p0.y = pack_bf16x2((v0.z - mean) * inv * w0.z + b0.z,
                       (v0.w - mean) * inv * w0.w + b0.w);
    p1.x = pack_bf16x2((v1.x - mean) * inv * w1.x + b1.x,
                       (v1.y - mean) * inv * w1.y + b1.y);
    p1.y = pack_bf16x2((v1.z - mean) * inv * w1.z + b1.z,
                       (v1.w - mean) * inv * w1.w + b1.w);
    *(uint2*)(o + c0) = p0;
    *(uint2*)(o + c1) = p1;
}

// ===================== BF16 tensor-core GEMM: 128x128x32, 3-stage ============
#define GAST 40
#define GBST 136
#define GA_BYTES (128 * GAST * 2)       // 10240
#define GB_BYTES (32 * GBST * 2)        // 8704
#define GSTAGE (GA_BYTES + GB_BYTES)    // 18944
#define GEMM_SMEM (3 * GSTAGE)          // 56832

__device__ __forceinline__ void gemm_load_tile(
    const __nv_bfloat16* __restrict__ A, const __nv_bfloat16* __restrict__ B,
    int K, int N, int m0, int n0, int k0, unsigned stg, int tid)
{
    #pragma unroll
    for (int i = 0; i < 2; ++i) {
        int id = tid + i * 256;
        int r = id >> 2, c = id & 3;
        CP_ASYNC16(stg + (unsigned)(r * 80 + c * 16),
                   A + (size_t)(m0 + r) * K + k0 + c * 8);
    }
    #pragma unroll
    for (int i = 0; i < 2; ++i) {
        int id = tid + i * 256;
        int r = id >> 4, c = id & 15;
        CP_ASYNC16(stg + (unsigned)GA_BYTES + (unsigned)(r * 272 + c * 16),
                   B + (size_t)(k0 + r) * N + n0 + c * 8);
    }
}

__global__ __launch_bounds__(256) void gemm_bf16(
    const __nv_bfloat16* __restrict__ A, const __nv_bfloat16* __restrict__ B,
    const float* __restrict__ R, float* __restrict__ Cf,
    __nv_bfloat16* __restrict__ Cb, int M, int N, int K)
{
    extern __shared__ char smc[];
    unsigned sb = (unsigned)__cvta_generic_to_shared(smc);

    int tid = threadIdx.x;
    int wid = tid >> 5, lane = tid & 31;
    int g = lane >> 2, tig = lane & 3;
    int wm = wid & 1, wn = wid >> 1;
    int m0 = blockIdx.y * 128, n0 = blockIdx.x * 128;
    int am = wm * 64, bn = wn * 32;

    float acc[4][4][4];
    #pragma unroll
    for (int i = 0; i < 4; ++i)
        #pragma unroll
        for (int j = 0; j < 4; ++j)
            #pragma unroll
            for (int r = 0; r < 4; ++r) acc[i][j][r] = 0.f;

    const int NT = K / 32;
    gemm_load_tile(A, B, K, N, m0, n0, 0, sb, tid);
    CP_COMMIT();
    gemm_load_tile(A, B, K, N, m0, n0, 32, sb + GSTAGE, tid);
    CP_COMMIT();

    int lrow = lane & 15, lhi = lane >> 4;

    for (int kt = 0; kt < NT; ++kt) {
        if (kt + 1 < NT) asm volatile("cp.async.wait_group 1;");
        else             asm volatile("cp.async.wait_group 0;");
        __syncthreads();

        if (kt + 2 < NT) {
            gemm_load_tile(A, B, K, N, m0, n0, (kt + 2) * 32,
                           sb + (unsigned)(((kt + 2) % 3) * GSTAGE), tid);
            CP_COMMIT();
        }

        unsigned sA = sb + (unsigned)((kt % 3) * GSTAGE);
        unsigned sB = sA + (unsigned)GA_BYTES;

        #pragma unroll
        for (int s = 0; s < 2; ++s) {
            int ksb = s * 32;
            unsigned a[4][4];
            #pragma unroll
            for (int i = 0; i < 4; ++i)
                LDM_X4(a[i][0], a[i][1], a[i][2], a[i][3],
                       sA + (unsigned)((am + i * 16 + lrow) * 80 + ksb + lhi * 16));
            unsigned bf[4][2];
            #pragma unroll
            for (int jp = 0; jp < 2; ++jp) {
                unsigned t0, t1, t2, t3;
                LDM_X4_T(t0, t1, t2, t3,
                         sB + (unsigned)((s * 16 + lrow) * 272 +
                                         (bn + jp * 16 + lhi * 8) * 2));
                bf[2 * jp][0] = t0; bf[2 * jp][1] = t1;
                bf[2 * jp + 1][0] = t2; bf[2 * jp + 1][1] = t3;
            }
            #pragma unroll
            for (int i = 0; i < 4; ++i)
                #pragma unroll
                for (int j = 0; j < 4; ++j)
                    mma_bf16(acc[i][j], a[i], bf[j]);
        }
        __syncthreads();
    }

    #pragma unroll
    for (int i = 0; i < 4; ++i) {
        int row0 = m0 + am + i * 16 + g;
        #pragma unroll
        for (int j = 0; j < 4; ++j) {
            int col = n0 + bn + j * 8 + 2 * tig;
            size_t idx0 = (size_t)row0 * N + col;
            size_t idx1 = idx0 + (size_t)8 * N;
            if (Cb) {
                *(unsigned*)(Cb + idx0) = pack_bf16x2(acc[i][j][0], acc[i][j][1]);
                *(unsigned*)(Cb + idx1) = pack_bf16x2(acc[i][j][2], acc[i][j][3]);
            } else {
                float2 o0 = make_float2(acc[i][j][0], acc[i][j][1]);
                float2 o1 = make_float2(acc[i][j][2], acc[i][j][3]);
                float2 r0 = *(const float2*)(R + idx0);
                float2 r1 = *(const float2*)(R + idx1);
                o0.x += r0.x; o0.y += r0.y;
                o1.x += r1.x; o1.y += r1.y;
                *(float2*)(Cf + idx0) = o0;
                *(float2*)(Cf + idx1) = o1;
            }
        }
    }
}

// ===================== RoPE in place on bf16 qkv =====================
__global__ __launch_bounds__(256) void rope_kernel(__nv_bfloat16* __restrict__ qkv)
{
    int t = blockIdx.x * blockDim.x + threadIdx.x;
    int i = t & 31;
    int h = (t >> 5) & 15;
    int s = (t >> 9) & 2047;
    int b = t >> 20;
    if (b >= B_SZ) return;

    size_t base = ((size_t)(b * S_LEN + s)) * D3 + h * DH;
    double th = (double)s * pow(10000.0, -(double)i / 32.0);
    float c = (float)cos(th), sn = (float)sin(th);

    __nv_bfloat162* q = (__nv_bfloat162*)(qkv + base + 2 * i);
    float x1 = __bfloat162float(q->x), x2 = __bfloat162float(q->y);
    *q = __floats2bfloat162_rn(x1 * c - x2 * sn, x2 * c + x1 * sn);

    __nv_bfloat162* k = (__nv_bfloat162*)(qkv + base + D_MODEL + 2 * i);
    x1 = __bfloat162float(k->x); x2 = __bfloat162float(k->y);
    *k = __floats2bfloat162_rn(x1 * c - x2 * sn, x2 * c + x1 * sn);
}

// ===================== FA2 attention: BQ=64, BK=32, Dh=128, 4 warps ===========
// Each warp owns 16 q-rows fully. S/P register-resident; Q frags hoisted.
// K and V double-buffered (one cp.async group per iter).
#define FQ_B 0u                        // Q: 64 x 272 B = 17408
#define FK_B 17408u                    // K: 2 x (32 x 272) = 17408
#define FV_B 34816u                    // V: 2 x (32 x 272) = 17408
#define FKV_TILE 8704u
#define ATTN_SMEM 52224

__global__ __launch_bounds__(128) void attn_kernel(
    const __nv_bfloat16* __restrict__ qkv, __nv_bfloat16* __restrict__ ctx)
{
    extern __shared__ char smc[];
    unsigned sb = (unsigned)__cvta_generic_to_shared(smc);

    int qt = blockIdx.x, h = blockIdx.y, b = blockIdx.z;
    int tid = threadIdx.x;
    int wid = tid >> 5, lane = tid & 31;
    int g = lane >> 2, tig = lane & 3;
    int lrow = lane & 15, lhi = lane >> 4;
    int q0 = qt * 64;
    const float SCALE = 0.0883883476483184f;  // 1/sqrt(128)

    // ---- prologue: Q (64x128), K(0), V(0) ----
    const __nv_bfloat16* qbase = qkv + ((size_t)(b * S_LEN + q0)) * D3 + h * DH;
    #pragma unroll
    for (int it = 0; it < 8; ++it) {
        int id = tid + it * 128;
        int r = id >> 4, c = id & 15;
        CP_ASYNC16(sb + FQ_B + (unsigned)(r * 272 + c * 16),
                   qbase + (size_t)r * D3 + c * 8);
    }
    {
        const __nv_bfloat16* kb = qkv + ((size_t)(b * S_LEN)) * D3 + D_MODEL + h * DH;
        const __nv_bfloat16* vb = qkv + ((size_t)(b * S_LEN)) * D3 + 2 * D_MODEL + h * DH;
        #pragma unroll
        for (int it = 0; it < 4; ++it) {
            int id = tid + it * 128;
            int r = id >> 4, c = id & 15;
            CP_ASYNC16(sb + FK_B + (unsigned)(r * 272 + c * 16), kb + (size_t)r * D3 + c * 8);
            CP_ASYNC16(sb + FV_B + (unsigned)(r * 272 + c * 16), vb + (size_t)r * D3 + c * 8);
        }
    }
    CP_COMMIT();
    asm volatile("cp.async.wait_group 0;");
    __syncthreads();

    // hoist Q fragments (warp wid owns rows 16*wid .. 16*wid+15)
    unsigned qa[8][4];
    #pragma unroll
    for (int s = 0; s < 8; ++s)
        LDM_X4(qa[s][0], qa[s][1], qa[s][2], qa[s][3],
               sb + FQ_B + (unsigned)((wid * 16 + lrow) * 272 + s * 32 + lhi * 16));

    float oacc[16][4];
    #pragma unroll
    for (int jn = 0; jn < 16; ++jn)
        #pragma unroll
        for (int r = 0; r < 4; ++r) oacc[jn][r] = 0.f;
    float m0 = -1e30f, m1 = -1e30f, l0 = 0.f, l1 = 0.f;

    const int NT = S_LEN / 32;
    for (int kt = 0; kt < NT; ++kt) {
        int buf = kt & 1;
        __syncthreads();   // all warps done reading buf^1 (iter kt-1)
        if (kt + 1 < NT) {
            unsigned nb = (unsigned)((buf ^ 1) * FKV_TILE);
            const __nv_bfloat16* kb = qkv + ((size_t)(b * S_LEN + (kt + 1) * 32)) * D3
                                      + D_MODEL + h * DH;
            const __nv_bfloat16* vb = kb + D_MODEL;
            #pragma unroll
            for (int it = 0; it < 4; ++it) {
                int id = tid + it * 128;
                int r = id >> 4, c = id & 15;
                CP_ASYNC16(sb + FK_B + nb + (unsigned)(r * 272 + c * 16),
                           kb + (size_t)r * D3 + c * 8);
                CP_ASYNC16(sb + FV_B + nb + (unsigned)(r * 272 + c * 16),
                           vb + (size_t)r * D3 + c * 8);
            }
            CP_COMMIT();
            asm volatile("cp.async.wait_group 1;");   // drain group for tile kt
        } else {
            asm volatile("cp.async.wait_group 0;");
        }
        __syncthreads();   // tile kt visible to all warps

        // ---- S = Q K^T : sc[j] covers keys 8j..8j+7 (j=0..3), rows g/g+8 ----
        float sc[4][4];
        #pragma unroll
        for (int j = 0; j < 4; ++j)
            #pragma unroll
            for (int r = 0; r < 4; ++r) sc[j][r] = 0.f;
        {
            unsigned sK = sb + FK_B + (unsigned)(buf * FKV_TILE);
            #pragma unroll
            for (int sp = 0; sp < 4; ++sp) {
                #pragma unroll
                for (int j = 0; j < 4; ++j) {
                    unsigned t0, t1, t2, t3;
                    LDM_X4(t0, t1, t2, t3,
                           sK + (unsigned)((j * 8 + (lane & 7)) * 272 +
                                           sp * 64 + (lane >> 3) * 16));
                    unsigned b0[2] = { t0, t1 }, b1[2] = { t2, t3 };
                    mma_bf16(sc[j], qa[2 * sp], b0);
                    mma_bf16(sc[j], qa[2 * sp + 1], b1);
                }
            }
        }

        // ---- register softmax (rows g and g+8) ----
        float mx0 = -1e30f, mx1 = -1e30f;
        #pragma unroll
        for (int j = 0; j < 4; ++j) {
            sc[j][0] *= SCALE; sc[j][1] *= SCALE;
            sc[j][2] *= SCALE; sc[j][3] *= SCALE;
            mx0 = fmaxf(mx0, fmaxf(sc[j][0], sc[j][1]));
            mx1 = fmaxf(mx1, fmaxf(sc[j][2], sc[j][3]));
        }
        mx0 = fmaxf(mx0, __shfl_xor_sync(0xffffffffu, mx0, 1));
        mx0 = fmaxf(mx0, __shfl_xor_sync(0xffffffffu, mx0, 2));
        mx1 = fmaxf(mx1, __shfl_xor_sync(0xffffffffu, mx1, 1));
        mx1 = fmaxf(mx1, __shfl_xor_sync(0xffffffffu, mx1, 2));
        float mn0 = fmaxf(m0, mx0), mn1 = fmaxf(m1, mx1);
        float corr0 = __expf(m0 - mn0), corr1 = __expf(m1 - mn1);
        float su0 = 0.f, su1 = 0.f;
        #pragma unroll
        for (int j = 0; j < 4; ++j) {
            sc[j][0] = __expf(sc[j][0] - mn0);
            sc[j][1] = __expf(sc[j][1] - mn0);
            sc[j][2] = __expf(sc[j][2] - mn1);
            sc[j][3] = __expf(sc[j][3] - mn1);
            su0 += sc[j][0] + sc[j][1];
            su1 += sc[j][2] + sc[j][3];
        }
        su0 += __shfl_xor_sync(0xffffffffu, su0, 1);
        su0 += __shfl_xor_sync(0xffffffffu, su0, 2);
        su1 += __shfl_xor_sync(0xffffffffu, su1, 1);
        su1 += __shfl_xor_sync(0xffffffffu, su1, 2);
        l0 = l0 * corr0 + su0;
        l1 = l1 * corr1 + su1;
        m0 = mn0; m1 = mn1;

        // pack P into PV a-frags: pk[s] = keys 16s..16s+15 (from sc[2s], sc[2s+1])
        unsigned pk[2][4];
        #pragma unroll
        for (int s = 0; s < 2; ++s) {
            pk[s][0] = pack_bf16x2(sc[2 * s][0],     sc[2 * s][1]);
            pk[s][1] = pack_bf16x2(sc[2 * s][2],     sc[2 * s][3]);
            pk[s][2] = pack_bf16x2(sc[2 * s + 1][0], sc[2 * s + 1][1]);
            pk[s][3] = pack_bf16x2(sc[2 * s + 1][2], sc[2 * s + 1][3]);
        }

        // ---- rescale O; O += P V ----
        #pragma unroll
        for (int jn = 0; jn < 16; ++jn) {
            oacc[jn][0] *= corr0; oacc[jn][1] *= corr0;
            oacc[jn][2] *= corr1; oacc[jn][3] *= corr1;
        }
        {
            unsigned sV = sb + FV_B + (unsigned)(buf * FKV_TILE);
            #pragma unroll
            for (int jn = 0; jn < 16; ++jn) {
                unsigned t0, t1, t2, t3;
                LDM_X4_T(t0, t1, t2, t3, sV + (unsigned)(lane * 272 + jn * 16));
                unsigned b0[2] = { t0, t1 }, b1[2] = { t2, t3 };
                mma_bf16(oacc[jn], pk[0], b0);
                mma_bf16(oacc[jn], pk[1], b1);
            }
        }
    }

    // ---- epilogue: O /= l, bf16 ----
    float inv0 = 1.0f / l0, inv1 = 1.0f / l1;
    int row = q0 + wid * 16 + g;
    #pragma unroll
    for (int jn = 0; jn < 16; ++jn) {
        int col = h * DH + jn * 8 + 2 * tig;
        size_t i0 = ((size_t)(b * S_LEN + row)) * D_MODEL + col;
        size_t i1 = i0 + (size_t)8 * D_MODEL;
        *(unsigned*)(ctx + i0) = pack_bf16x2(oacc[jn][0] * inv0, oacc[jn][1] * inv0);
        *(unsigned*)(ctx + i1) = pack_bf16x2(oacc[jn][2] * inv1, oacc[jn][3] * inv1);
    }
}

// ===================== launcher =====================
extern "C" void kernel_launch(void* const* d_in, const int* in_sizes, int n_in,
                              void* d_out, int out_size)
{
    const float* X     = (const float*)d_in[0];
    const float* ln_w  = (const float*)d_in[1];
    const float* ln_b  = (const float*)d_in[2];
    const float* W_in  = (const float*)d_in[3];
    const float* W_out = (const float*)d_in[4];
    float* out = (float*)d_out;

    __nv_bfloat16 *xn, *qkv, *ctx, *win, *wout;
    cudaGetSymbolAddress((void**)&xn,   g_xn);
    cudaGetSymbolAddress((void**)&qkv,  g_qkv);
    cudaGetSymbolAddress((void**)&ctx,  g_ctx);
    cudaGetSymbolAddress((void**)&win,  g_win);
    cudaGetSymbolAddress((void**)&wout, g_wout);

    {
        int n1 = D_MODEL * D3;
        int n2 = D_MODEL * D_MODEL;
        wcvt_kernel<<<n1 / 2048, 256>>>(W_in,  win,  n1);
        wcvt_kernel<<<n2 / 2048, 256>>>(W_out, wout, n2);
    }

    ln_kernel<<<NTOK, 256>>>(X, ln_w, ln_b, xn);

    cudaFuncSetAttribute(gemm_bf16, cudaFuncAttributeMaxDynamicSharedMemorySize, GEMM_SMEM);

    dim3 g1(D3 / 128, NTOK / 128);
    gemm_bf16<<<g1, 256, GEMM_SMEM>>>(xn, win, nullptr, nullptr, qkv, NTOK, D3, D_MODEL);

    rope_kernel<<<(B_SZ * S_LEN * H_NUM * 32) / 256, 256>>>(qkv);

    cudaFuncSetAttribute(attn_kernel, cudaFuncAttributeMaxDynamicSharedMemorySize, ATTN_SMEM);
    attn_kernel<<<dim3(S_LEN / 64, H_NUM, B_SZ), 128, ATTN_SMEM>>>(qkv, ctx);

    dim3 g2(D_MODEL / 128, NTOK / 128);
    gemm_bf16<<<g2, 256, GEMM_SMEM>>>(ctx, wout, X, out, nullptr, NTOK, D_MODEL, D_MODEL);
}

// round 11
// speedup vs baseline: 4.7941x; 1.0512x over previous
#include <cuda_runtime.h>
#include <cuda_bf16.h>
#include <math.h>

#define B_SZ 4
#define S_LEN 2048
#define D_MODEL 2048
#define H_NUM 16
#define DH 128
#define D3 6144
#define NTOK (B_SZ * S_LEN)   // 8192

// -------- scratch (allocation-free rule: __device__ globals) --------
__device__ __nv_bfloat16 g_xn  [(size_t)NTOK * D_MODEL];     // 32 MB
__device__ __nv_bfloat16 g_qkv [(size_t)NTOK * D3];          // 100 MB
__device__ __nv_bfloat16 g_ctx [(size_t)NTOK * D_MODEL];     // 32 MB
__device__ __nv_bfloat16 g_win [(size_t)D_MODEL * D3];       // 24 MB
__device__ __nv_bfloat16 g_wout[(size_t)D_MODEL * D_MODEL];  // 8 MB

// ---------- helpers ----------
#define CP_ASYNC16(dst, src) \
    asm volatile("cp.async.cg.shared.global [%0], [%1], 16;" :: "r"(dst), "l"(src))
#define CP_COMMIT() asm volatile("cp.async.commit_group;")

#define LDM_X4(r0, r1, r2, r3, addr) \
    asm volatile("ldmatrix.sync.aligned.m8n8.x4.shared.b16 {%0,%1,%2,%3}, [%4];" \
        : "=r"(r0), "=r"(r1), "=r"(r2), "=r"(r3) : "r"(addr))
#define LDM_X4_T(r0, r1, r2, r3, addr) \
    asm volatile("ldmatrix.sync.aligned.m8n8.x4.trans.shared.b16 {%0,%1,%2,%3}, [%4];" \
        : "=r"(r0), "=r"(r1), "=r"(r2), "=r"(r3) : "r"(addr))

__device__ __forceinline__ void mma_bf16(float* c, const unsigned* a, const unsigned* b) {
    asm volatile(
        "mma.sync.aligned.m16n8k16.row.col.f32.bf16.bf16.f32 "
        "{%0,%1,%2,%3}, {%4,%5,%6,%7}, {%8,%9}, {%0,%1,%2,%3};"
        : "+f"(c[0]), "+f"(c[1]), "+f"(c[2]), "+f"(c[3])
        : "r"(a[0]), "r"(a[1]), "r"(a[2]), "r"(a[3]), "r"(b[0]), "r"(b[1]));
}

__device__ __forceinline__ unsigned pack_bf16x2(float lo, float hi) {
    unsigned r;
    asm("cvt.rn.bf16x2.f32 %0, %1, %2;" : "=r"(r) : "f"(hi), "f"(lo));
    return r;
}

// ===================== weight fp32 -> bf16 =====================
__global__ __launch_bounds__(256) void wcvt_kernel(
    const float* __restrict__ in, __nv_bfloat16* __restrict__ out, int n)
{
    int i = (blockIdx.x * 256 + threadIdx.x) * 8;
    if (i >= n) return;
    float4 v0 = *(const float4*)(in + i);
    float4 v1 = *(const float4*)(in + i + 4);
    uint4 o;
    o.x = pack_bf16x2(v0.x, v0.y);
    o.y = pack_bf16x2(v0.z, v0.w);
    o.z = pack_bf16x2(v1.x, v1.y);
    o.w = pack_bf16x2(v1.z, v1.w);
    *(uint4*)(out + i) = o;
}

// ===================== LayerNorm (bf16 output) =====================
__global__ __launch_bounds__(256) void ln_kernel(
    const float* __restrict__ X, const float* __restrict__ w,
    const float* __restrict__ b, __nv_bfloat16* __restrict__ out)
{
    int row = blockIdx.x;
    int t = threadIdx.x;
    int lane = t & 31, wrp = t >> 5;
    const float* x = X + (size_t)row * D_MODEL;

    float4 v0 = *(const float4*)(x + t * 4);
    float4 v1 = *(const float4*)(x + 1024 + t * 4);

    float s  = v0.x + v0.y + v0.z + v0.w + v1.x + v1.y + v1.z + v1.w;
    float sq = v0.x*v0.x + v0.y*v0.y + v0.z*v0.z + v0.w*v0.w
             + v1.x*v1.x + v1.y*v1.y + v1.z*v1.z + v1.w*v1.w;

    #pragma unroll
    for (int off = 16; off; off >>= 1) {
        s  += __shfl_xor_sync(0xffffffffu, s,  off);
        sq += __shfl_xor_sync(0xffffffffu, sq, off);
    }
    __shared__ float sh_s[8], sh_q[8];
    if (lane == 0) { sh_s[wrp] = s; sh_q[wrp] = sq; }
    __syncthreads();
    float tot = 0.f, totq = 0.f;
    #pragma unroll
    for (int i = 0; i < 8; ++i) { tot += sh_s[i]; totq += sh_q[i]; }
    float mean = tot * (1.0f / D_MODEL);
    float var  = totq * (1.0f / D_MODEL) - mean * mean;
    float inv  = rsqrtf(var + 1e-5f);

    __nv_bfloat16* o = out + (size_t)row * D_MODEL;
    int c0 = t * 4, c1 = 1024 + t * 4;
    float4 w0 = *(const float4*)(w + c0), w1 = *(const float4*)(w + c1);
    float4 b0 = *(const float4*)(b + c0), b1 = *(const float4*)(b + c1);
    uint2 p0, p1;
    p0.x = pack_bf16x2((v0.x - mean) * inv * w0.x + b0.x,
                       (v0.y - mean) * inv * w0.y + b0.y);
    p0.y = pack_bf16x2((v0.z - mean) * inv * w0.z + b0.z,
                       (v0.w - mean) * inv * w0.w + b0.w);
    p1.x = pack_bf16x2((v1.x - mean) * inv * w1.x + b1.x,
                       (v1.y - mean) * inv * w1.y + b1.y);
    p1.y = pack_bf16x2((v1.z - mean) * inv * w1.z + b1.z,
                       (v1.w - mean) * inv * w1.w + b1.w);
    *(uint2*)(o + c0) = p0;
    *(uint2*)(o + c1) = p1;
}

// ===================== BF16 GEMM: 128x128x32, 4-stage, 1 sync/tile ===========
#define GAST 40
#define GBST 136
#define GA_BYTES (128 * GAST * 2)       // 10240
#define GB_BYTES (32 * GBST * 2)        // 8704
#define GSTAGE (GA_BYTES + GB_BYTES)    // 18944
#define GEMM_SMEM (4 * GSTAGE)          // 75776

__device__ __forceinline__ void gemm_load_tile(
    const __nv_bfloat16* __restrict__ A, const __nv_bfloat16* __restrict__ B,
    int K, int N, int m0, int n0, int k0, unsigned stg, int tid)
{
    #pragma unroll
    for (int i = 0; i < 2; ++i) {
        int id = tid + i * 256;
        int r = id >> 2, c = id & 3;
        CP_ASYNC16(stg + (unsigned)(r * 80 + c * 16),
                   A + (size_t)(m0 + r) * K + k0 + c * 8);
    }
    #pragma unroll
    for (int i = 0; i < 2; ++i) {
        int id = tid + i * 256;
        int r = id >> 4, c = id & 15;
        CP_ASYNC16(stg + (unsigned)GA_BYTES + (unsigned)(r * 272 + c * 16),
                   B + (size_t)(k0 + r) * N + n0 + c * 8);
    }
}

__global__ __launch_bounds__(256) void gemm_bf16(
    const __nv_bfloat16* __restrict__ A, const __nv_bfloat16* __restrict__ B,
    const float* __restrict__ R, float* __restrict__ Cf,
    __nv_bfloat16* __restrict__ Cb, int M, int N, int K)
{
    extern __shared__ char smc[];
    unsigned sb = (unsigned)__cvta_generic_to_shared(smc);

    int tid = threadIdx.x;
    int wid = tid >> 5, lane = tid & 31;
    int g = lane >> 2, tig = lane & 3;
    int wm = wid & 1, wn = wid >> 1;
    int m0 = blockIdx.y * 128, n0 = blockIdx.x * 128;
    int am = wm * 64, bn = wn * 32;

    float acc[4][4][4];
    #pragma unroll
    for (int i = 0; i < 4; ++i)
        #pragma unroll
        for (int j = 0; j < 4; ++j)
            #pragma unroll
            for (int r = 0; r < 4; ++r) acc[i][j][r] = 0.f;

    const int NT = K / 32;
    gemm_load_tile(A, B, K, N, m0, n0, 0, sb, tid);
    CP_COMMIT();
    gemm_load_tile(A, B, K, N, m0, n0, 32, sb + GSTAGE, tid);
    CP_COMMIT();
    gemm_load_tile(A, B, K, N, m0, n0, 64, sb + 2 * GSTAGE, tid);
    CP_COMMIT();

    int lrow = lane & 15, lhi = lane >> 4;

    for (int kt = 0; kt < NT; ++kt) {
        if (kt <= NT - 3)      asm volatile("cp.async.wait_group 2;");
        else if (kt == NT - 2) asm volatile("cp.async.wait_group 1;");
        else                   asm volatile("cp.async.wait_group 0;");
        __syncthreads();   // stage kt%4 ready; all warps done reading (kt+3)%4

        if (kt + 3 < NT) {
            gemm_load_tile(A, B, K, N, m0, n0, (kt + 3) * 32,
                           sb + (unsigned)(((kt + 3) & 3) * GSTAGE), tid);
            CP_COMMIT();
        }

        unsigned sA = sb + (unsigned)((kt & 3) * GSTAGE);
        unsigned sB = sA + (unsigned)GA_BYTES;

        #pragma unroll
        for (int s = 0; s < 2; ++s) {
            int ksb = s * 32;
            unsigned a[4][4];
            #pragma unroll
            for (int i = 0; i < 4; ++i)
                LDM_X4(a[i][0], a[i][1], a[i][2], a[i][3],
                       sA + (unsigned)((am + i * 16 + lrow) * 80 + ksb + lhi * 16));
            unsigned bf[4][2];
            #pragma unroll
            for (int jp = 0; jp < 2; ++jp) {
                unsigned t0, t1, t2, t3;
                LDM_X4_T(t0, t1, t2, t3,
                         sB + (unsigned)((s * 16 + lrow) * 272 +
                                         (bn + jp * 16 + lhi * 8) * 2));
                bf[2 * jp][0] = t0; bf[2 * jp][1] = t1;
                bf[2 * jp + 1][0] = t2; bf[2 * jp + 1][1] = t3;
            }
            #pragma unroll
            for (int i = 0; i < 4; ++i)
                #pragma unroll
                for (int j = 0; j < 4; ++j)
                    mma_bf16(acc[i][j], a[i], bf[j]);
        }
        // no bottom sync: 4-stage ring + top barrier make it redundant
    }

    #pragma unroll
    for (int i = 0; i < 4; ++i) {
        int row0 = m0 + am + i * 16 + g;
        #pragma unroll
        for (int j = 0; j < 4; ++j) {
            int col = n0 + bn + j * 8 + 2 * tig;
            size_t idx0 = (size_t)row0 * N + col;
            size_t idx1 = idx0 + (size_t)8 * N;
            if (Cb) {
                *(unsigned*)(Cb + idx0) = pack_bf16x2(acc[i][j][0], acc[i][j][1]);
                *(unsigned*)(Cb + idx1) = pack_bf16x2(acc[i][j][2], acc[i][j][3]);
            } else {
                float2 o0 = make_float2(acc[i][j][0], acc[i][j][1]);
                float2 o1 = make_float2(acc[i][j][2], acc[i][j][3]);
                float2 r0 = *(const float2*)(R + idx0);
                float2 r1 = *(const float2*)(R + idx1);
                o0.x += r0.x; o0.y += r0.y;
                o1.x += r1.x; o1.y += r1.y;
                *(float2*)(Cf + idx0) = o0;
                *(float2*)(Cf + idx1) = o1;
            }
        }
    }
}

// ===================== RoPE in place on bf16 qkv =====================
__global__ __launch_bounds__(256) void rope_kernel(__nv_bfloat16* __restrict__ qkv)
{
    int t = blockIdx.x * blockDim.x + threadIdx.x;
    int i = t & 31;
    int h = (t >> 5) & 15;
    int s = (t >> 9) & 2047;
    int b = t >> 20;
    if (b >= B_SZ) return;

    size_t base = ((size_t)(b * S_LEN + s)) * D3 + h * DH;
    double th = (double)s * pow(10000.0, -(double)i / 32.0);
    float c = (float)cos(th), sn = (float)sin(th);

    __nv_bfloat162* q = (__nv_bfloat162*)(qkv + base + 2 * i);
    float x1 = __bfloat162float(q->x), x2 = __bfloat162float(q->y);
    *q = __floats2bfloat162_rn(x1 * c - x2 * sn, x2 * c + x1 * sn);

    __nv_bfloat162* k = (__nv_bfloat162*)(qkv + base + D_MODEL + 2 * i);
    x1 = __bfloat162float(k->x); x2 = __bfloat162float(k->y);
    *k = __floats2bfloat162_rn(x1 * c - x2 * sn, x2 * c + x1 * sn);
}

// ===================== FA2 attention: BQ=64, BK=64, Dh=128, 4 warps ===========
// Each warp owns 16 q-rows. S/P register-resident; softmax in log2 domain.
// K and V double-buffered (one cp.async group per iter).
#define FQ_B 0u                        // Q: 64 x 272 B = 17408
#define FK_B 17408u                    // K: 2 x (64 x 272) = 34816
#define FV_B 52224u                    // V: 2 x (64 x 272) = 34816
#define FKV_TILE 17408u
#define ATTN_SMEM 87040

__global__ __launch_bounds__(128) void attn_kernel(
    const __nv_bfloat16* __restrict__ qkv, __nv_bfloat16* __restrict__ ctx)
{
    extern __shared__ char smc[];
    unsigned sb = (unsigned)__cvta_generic_to_shared(smc);

    int qt = blockIdx.x, h = blockIdx.y, b = blockIdx.z;
    int tid = threadIdx.x;
    int wid = tid >> 5, lane = tid & 31;
    int g = lane >> 2, tig = lane & 3;
    int lrow = lane & 15, lhi = lane >> 4;
    int q0 = qt * 64;
    const float SC2 = 0.1275174265f;   // (1/sqrt(128)) * log2(e)

    // ---- prologue: Q (64x128), K(0) (64x128), V(0) (64x128) ----
    const __nv_bfloat16* qbase = qkv + ((size_t)(b * S_LEN + q0)) * D3 + h * DH;
    #pragma unroll
    for (int it = 0; it < 8; ++it) {
        int id = tid + it * 128;
        int r = id >> 4, c = id & 15;
        CP_ASYNC16(sb + FQ_B + (unsigned)(r * 272 + c * 16),
                   qbase + (size_t)r * D3 + c * 8);
    }
    {
        const __nv_bfloat16* kb = qkv + ((size_t)(b * S_LEN)) * D3 + D_MODEL + h * DH;
        const __nv_bfloat16* vb = kb + D_MODEL;
        #pragma unroll
        for (int it = 0; it < 8; ++it) {
            int id = tid + it * 128;
            int r = id >> 4, c = id & 15;
            CP_ASYNC16(sb + FK_B + (unsigned)(r * 272 + c * 16), kb + (size_t)r * D3 + c * 8);
            CP_ASYNC16(sb + FV_B + (unsigned)(r * 272 + c * 16), vb + (size_t)r * D3 + c * 8);
        }
    }
    CP_COMMIT();
    asm volatile("cp.async.wait_group 0;");
    __syncthreads();

    // hoist Q fragments (warp wid owns rows 16*wid .. 16*wid+15)
    unsigned qa[8][4];
    #pragma unroll
    for (int s = 0; s < 8; ++s)
        LDM_X4(qa[s][0], qa[s][1], qa[s][2], qa[s][3],
               sb + FQ_B + (unsigned)((wid * 16 + lrow) * 272 + s * 32 + lhi * 16));

    float oacc[16][4];
    #pragma unroll
    for (int jn = 0; jn < 16; ++jn)
        #pragma unroll
        for (int r = 0; r < 4; ++r) oacc[jn][r] = 0.f;
    float m0 = -1e30f, m1 = -1e30f, l0 = 0.f, l1 = 0.f;

    const int NT = S_LEN / 64;
    for (int kt = 0; kt < NT; ++kt) {
        int buf = kt & 1;
        __syncthreads();   // all warps done reading buf^1 (iter kt-1)
        if (kt + 1 < NT) {
            unsigned nb = (unsigned)((buf ^ 1) * FKV_TILE);
            const __nv_bfloat16* kb = qkv + ((size_t)(b * S_LEN + (kt + 1) * 64)) * D3
                                      + D_MODEL + h * DH;
            const __nv_bfloat16* vb = kb + D_MODEL;
            #pragma unroll
            for (int it = 0; it < 8; ++it) {
                int id = tid + it * 128;
                int r = id >> 4, c = id & 15;
                CP_ASYNC16(sb + FK_B + nb + (unsigned)(r * 272 + c * 16),
                           kb + (size_t)r * D3 + c * 8);
                CP_ASYNC16(sb + FV_B + nb + (unsigned)(r * 272 + c * 16),
                           vb + (size_t)r * D3 + c * 8);
            }
            CP_COMMIT();
            asm volatile("cp.async.wait_group 1;");   // tile kt resident
        } else {
            asm volatile("cp.async.wait_group 0;");
        }
        __syncthreads();

        // ---- S = Q K^T : sc[j] covers keys 8j..8j+7 (j=0..7), rows g/g+8 ----
        float sc[8][4];
        #pragma unroll
        for (int j = 0; j < 8; ++j)
            #pragma unroll
            for (int r = 0; r < 4; ++r) sc[j][r] = 0.f;
        {
            unsigned sK = sb + FK_B + (unsigned)(buf * FKV_TILE);
            #pragma unroll
            for (int sp = 0; sp < 4; ++sp) {
                #pragma unroll
                for (int j = 0; j < 8; ++j) {
                    unsigned t0, t1, t2, t3;
                    LDM_X4(t0, t1, t2, t3,
                           sK + (unsigned)((j * 8 + (lane & 7)) * 272 +
                                           sp * 64 + (lane >> 3) * 16));
                    unsigned b0[2] = { t0, t1 }, b1[2] = { t2, t3 };
                    mma_bf16(sc[j], qa[2 * sp], b0);
                    mma_bf16(sc[j], qa[2 * sp + 1], b1);
                }
            }
        }

        // ---- register softmax in log2 domain (rows g, g+8) ----
        float mx0 = -1e30f, mx1 = -1e30f;
        #pragma unroll
        for (int j = 0; j < 8; ++j) {
            sc[j][0] *= SC2; sc[j][1] *= SC2;
            sc[j][2] *= SC2; sc[j][3] *= SC2;
            mx0 = fmaxf(mx0, fmaxf(sc[j][0], sc[j][1]));
            mx1 = fmaxf(mx1, fmaxf(sc[j][2], sc[j][3]));
        }
        mx0 = fmaxf(mx0, __shfl_xor_sync(0xffffffffu, mx0, 1));
        mx0 = fmaxf(mx0, __shfl_xor_sync(0xffffffffu, mx0, 2));
        mx1 = fmaxf(mx1, __shfl_xor_sync(0xffffffffu, mx1, 1));
        mx1 = fmaxf(mx1, __shfl_xor_sync(0xffffffffu, mx1, 2));
        float mn0 = fmaxf(m0, mx0), mn1 = fmaxf(m1, mx1);
        float corr0 = exp2f(m0 - mn0), corr1 = exp2f(m1 - mn1);
        float su0 = 0.f, su1 = 0.f;
        #pragma unroll
        for (int j = 0; j < 8; ++j) {
            sc[j][0] = exp2f(sc[j][0] - mn0);
            sc[j][1] = exp2f(sc[j][1] - mn0);
            sc[j][2] = exp2f(sc[j][2] - mn1);
            sc[j][3] = exp2f(sc[j][3] - mn1);
            su0 += sc[j][0] + sc[j][1];
            su1 += sc[j][2] + sc[j][3];
        }
        su0 += __shfl_xor_sync(0xffffffffu, su0, 1);
        su0 += __shfl_xor_sync(0xffffffffu, su0, 2);
        su1 += __shfl_xor_sync(0xffffffffu, su1, 1);
        su1 += __shfl_xor_sync(0xffffffffu, su1, 2);
        l0 = l0 * corr0 + su0;
        l1 = l1 * corr1 + su1;
        m0 = mn0; m1 = mn1;

        // pack P: pk[s] = keys 16s..16s+15
        unsigned pk[4][4];
        #pragma unroll
        for (int s = 0; s < 4; ++s) {
            pk[s][0] = pack_bf16x2(sc[2 * s][0],     sc[2 * s][1]);
            pk[s][1] = pack_bf16x2(sc[2 * s][2],     sc[2 * s][3]);
            pk[s][2] = pack_bf16x2(sc[2 * s + 1][0], sc[2 * s + 1][1]);
            pk[s][3] = pack_bf16x2(sc[2 * s + 1][2], sc[2 * s + 1][3]);
        }

        // ---- rescale O; O += P V (64 keys) ----
        #pragma unroll
        for (int jn = 0; jn < 16; ++jn) {
            oacc[jn][0] *= corr0; oacc[jn][1] *= corr0;
            oacc[jn][2] *= corr1; oacc[jn][3] *= corr1;
        }
        {
            unsigned sV = sb + FV_B + (unsigned)(buf * FKV_TILE);
            #pragma unroll
            for (int jn = 0; jn < 16; ++jn) {
                unsigned t0, t1, t2, t3;
                LDM_X4_T(t0, t1, t2, t3, sV + (unsigned)(lane * 272 + jn * 16));
                unsigned b0[2] = { t0, t1 }, b1[2] = { t2, t3 };
                mma_bf16(oacc[jn], pk[0], b0);
                mma_bf16(oacc[jn], pk[1], b1);
                LDM_X4_T(t0, t1, t2, t3, sV + (unsigned)((32 + lane) * 272 + jn * 16));
                unsigned b2[2] = { t0, t1 }, b3[2] = { t2, t3 };
                mma_bf16(oacc[jn], pk[2], b2);
                mma_bf16(oacc[jn], pk[3], b3);
            }
        }
    }

    // ---- epilogue: O /= l, bf16 ----
    float inv0 = 1.0f / l0, inv1 = 1.0f / l1;
    int row = q0 + wid * 16 + g;
    #pragma unroll
    for (int jn = 0; jn < 16; ++jn) {
        int col = h * DH + jn * 8 + 2 * tig;
        size_t i0 = ((size_t)(b * S_LEN + row)) * D_MODEL + col;
        size_t i1 = i0 + (size_t)8 * D_MODEL;
        *(unsigned*)(ctx + i0) = pack_bf16x2(oacc[jn][0] * inv0, oacc[jn][1] * inv0);
        *(unsigned*)(ctx + i1) = pack_bf16x2(oacc[jn][2] * inv1, oacc[jn][3] * inv1);
    }
}

// ===================== launcher =====================
extern "C" void kernel_launch(void* const* d_in, const int* in_sizes, int n_in,
                              void* d_out, int out_size)
{
    const float* X     = (const float*)d_in[0];
    const float* ln_w  = (const float*)d_in[1];
    const float* ln_b  = (const float*)d_in[2];
    const float* W_in  = (const float*)d_in[3];
    const float* W_out = (const float*)d_in[4];
    float* out = (float*)d_out;

    __nv_bfloat16 *xn, *qkv, *ctx, *win, *wout;
    cudaGetSymbolAddress((void**)&xn,   g_xn);
    cudaGetSymbolAddress((void**)&qkv,  g_qkv);
    cudaGetSymbolAddress((void**)&ctx,  g_ctx);
    cudaGetSymbolAddress((void**)&win,  g_win);
    cudaGetSymbolAddress((void**)&wout, g_wout);

    {
        int n1 = D_MODEL * D3;
        int n2 = D_MODEL * D_MODEL;
        wcvt_kernel<<<n1 / 2048, 256>>>(W_in,  win,  n1);
        wcvt_kernel<<<n2 / 2048, 256>>>(W_out, wout, n2);
    }

    ln_kernel<<<NTOK, 256>>>(X, ln_w, ln_b, xn);

    cudaFuncSetAttribute(gemm_bf16, cudaFuncAttributeMaxDynamicSharedMemorySize, GEMM_SMEM);

    dim3 g1(D3 / 128, NTOK / 128);
    gemm_bf16<<<g1, 256, GEMM_SMEM>>>(xn, win, nullptr, nullptr, qkv, NTOK, D3, D_MODEL);

    rope_kernel<<<(B_SZ * S_LEN * H_NUM * 32) / 256, 256>>>(qkv);

    cudaFuncSetAttribute(attn_kernel, cudaFuncAttributeMaxDynamicSharedMemorySize, ATTN_SMEM);
    attn_kernel<<<dim3(S_LEN / 64, H_NUM, B_SZ), 128, ATTN_SMEM>>>(qkv, ctx);

    dim3 g2(D_MODEL / 128, NTOK / 128);
    gemm_bf16<<<g2, 256, GEMM_SMEM>>>(ctx, wout, X, out, nullptr, NTOK, D_MODEL, D_MODEL);
}